// round 6
// baseline (speedup 1.0000x reference)
#include <cuda_runtime.h>
#include <cstdint>
#include <math.h>

#define Bb 2
#define Tt 2048
#define Cc 2048
#define Hh 16
#define Dd 128
#define NTOK (Bb*Tt)   // 4096

// Scratch (device globals: no runtime allocation allowed)
__device__ float g_q[(size_t)NTOK*Cc];
__device__ float g_k[(size_t)NTOK*Cc];
__device__ float g_v[(size_t)NTOK*Cc];
__device__ float g_ctx[(size_t)NTOK*Cc];
__device__ float g_xr[(size_t)NTOK*Cc];
__device__ float g_wq[(size_t)Cc*Cc];
__device__ float g_wk[(size_t)Cc*Cc];
__device__ float g_wv[(size_t)Cc*Cc];
__device__ float g_wp[(size_t)Cc*Cc];

// ===========================================================================
// helpers
// ===========================================================================
__device__ __forceinline__ uint32_t smem_u32(const void* p) {
    uint32_t a;
    asm("{ .reg .u64 t; cvta.to.shared.u64 t, %1; cvt.u32.u64 %0, t; }" : "=r"(a) : "l"(p));
    return a;
}
__device__ __forceinline__ void cp_async16(uint32_t dst, const void* src) {
    asm volatile("cp.async.cg.shared.global [%0], [%1], 16;" :: "r"(dst), "l"(src) : "memory");
}
__device__ __forceinline__ void cp_commit() {
    asm volatile("cp.async.commit_group;" ::: "memory");
}
__device__ __forceinline__ void cp_wait1() {
    asm volatile("cp.async.wait_group 1;" ::: "memory");
}
__device__ __forceinline__ void cp_wait0() {
    asm volatile("cp.async.wait_group 0;" ::: "memory");
}
__device__ __forceinline__ float rtf32(float x) {
    uint32_t o;
    asm("cvt.rna.tf32.f32 %0, %1;" : "=r"(o) : "f"(x));
    return __uint_as_float(o);
}
__device__ __forceinline__ uint32_t rtf32u(float x) {
    uint32_t o;
    asm("cvt.rna.tf32.f32 %0, %1;" : "=r"(o) : "f"(x));
    return o;
}
// m16n8k8 TF32 MMA, fp32 accumulate. A row-major [16x8], B col-major (stored [n][k]).
__device__ __forceinline__ void mma_tf32(float* c, const uint32_t* a, const uint32_t* b) {
    asm volatile(
        "mma.sync.aligned.m16n8k8.row.col.f32.tf32.tf32.f32 "
        "{%0,%1,%2,%3}, {%4,%5,%6,%7}, {%8,%9}, {%0,%1,%2,%3};"
        : "+f"(c[0]), "+f"(c[1]), "+f"(c[2]), "+f"(c[3])
        : "r"(a[0]), "r"(a[1]), "r"(a[2]), "r"(a[3]), "r"(b[0]), "r"(b[1]));
}

// ===========================================================================
// Fused round-to-TF32 preprocessing (z selects buffer)
// ===========================================================================
__global__ void __launch_bounds__(256) round_tf32_all(
    const float4* __restrict__ x,  float4* __restrict__ xr,
    const float4* __restrict__ w0, float4* __restrict__ r0,
    const float4* __restrict__ w1, float4* __restrict__ r1,
    const float4* __restrict__ w2, float4* __restrict__ r2,
    const float4* __restrict__ w3, float4* __restrict__ r3)
{
    const int z = blockIdx.z;
    const float4* src; float4* dst; int n4;
    if      (z == 0) { src = x;  dst = xr; n4 = NTOK*Cc/4; }
    else if (z == 1) { src = w0; dst = r0; n4 = Cc*Cc/4; }
    else if (z == 2) { src = w1; dst = r1; n4 = Cc*Cc/4; }
    else if (z == 3) { src = w2; dst = r2; n4 = Cc*Cc/4; }
    else             { src = w3; dst = r3; n4 = Cc*Cc/4; }
    int i = blockIdx.x * blockDim.x + threadIdx.x;
    if (i < n4) {
        float4 v = src[i];
        v.x = rtf32(v.x); v.y = rtf32(v.y); v.z = rtf32(v.z); v.w = rtf32(v.w);
        dst[i] = v;
    }
}

// ===========================================================================
// TF32 mma.sync GEMM: C[m,n] = sum_k A[m,k]*W[n,k] (+ bias[n])
// CTA 128x256, 8 warps, warp tile 64x64 (2m x 4n), BK=32, 3-stage cp.async.
// smem XOR-swizzled. 144KB smem -> 1 CTA/SM.
// ===========================================================================
#define G_BK     32
#define G_STAGES 3
#define G_ATSZ   (128*G_BK)            // 4096 floats
#define G_BTSZ   (256*G_BK)            // 8192 floats
#define G_SMEM   (G_STAGES*(G_ATSZ+G_BTSZ)*4)   // 147456 bytes
#define G_NSTEP  (Cc / G_BK)           // 64

template<bool BIAS, bool ROUND>
__device__ __forceinline__ void gemm_body(const float* __restrict__ A,
                                          const float* __restrict__ W,
                                          const float* __restrict__ bias,
                                          float* __restrict__ C)
{
    extern __shared__ float sm[];
    float* As = sm;                          // [3][128*32]
    float* Bs = sm + G_STAGES * G_ATSZ;      // [3][256*32]
    const uint32_t asb = smem_u32(As);
    const uint32_t bsb = smem_u32(Bs);

    const int tid  = threadIdx.x;
    const int lane = tid & 31;
    const int warp = tid >> 5;
    const int n0 = blockIdx.x * 256;
    const int m0 = blockIdx.y * 128;
    const int wm = (warp & 1) * 64;
    const int wn = (warp >> 1) * 64;
    const int fr = lane >> 2;
    const int fc = lane & 3;

    // loaders: A 128 rows x 8 chunks (2 thr/row, 4 chunks each); B 256 rows x 8 chunks
    const int lrA = tid >> 1;
    const int ljA = (tid & 1) * 4;
    const float* Ag = A + (size_t)(m0 + lrA) * Cc;
    const float* Wg = W + (size_t)(n0 + tid) * Cc;
    const uint32_t swA = (uint32_t)(lrA & 7);
    const uint32_t swB = (uint32_t)(tid & 7);

    float acc[4][8][4];
    #pragma unroll
    for (int i = 0; i < 4; i++)
        #pragma unroll
        for (int j = 0; j < 8; j++)
            #pragma unroll
            for (int q = 0; q < 4; q++) acc[i][j][q] = 0.f;

    #define G_LOAD(s, st) do {                                                  \
        const uint32_t sa = asb + (st) * (G_ATSZ*4);                             \
        const uint32_t sb = bsb + (st) * (G_BTSZ*4);                             \
        const int kof = (s) * G_BK;                                              \
        _Pragma("unroll")                                                        \
        for (int j = 0; j < 4; j++) {                                            \
            const int ch = ljA + j;                                              \
            cp_async16(sa + (lrA*32 + (((uint32_t)ch ^ swA) << 2)) * 4,          \
                       Ag + kof + ch*4);                                         \
        }                                                                        \
        _Pragma("unroll")                                                        \
        for (int j = 0; j < 8; j++) {                                            \
            cp_async16(sb + (tid*32 + (((uint32_t)j ^ swB) << 2)) * 4,           \
                       Wg + kof + j*4);                                          \
        }                                                                        \
    } while (0)

    G_LOAD(0, 0); cp_commit();
    G_LOAD(1, 1); cp_commit();

    for (int s = 0; s < G_NSTEP; s++) {
        cp_wait1();
        __syncthreads();
        if (s + 2 < G_NSTEP) { G_LOAD(s + 2, (s + 2) % G_STAGES); }
        cp_commit();

        const float* A_s = As + (s % G_STAGES) * G_ATSZ;
        const float* B_s = Bs + (s % G_STAGES) * G_BTSZ;

        #pragma unroll
        for (int ks = 0; ks < 4; ks++) {
            const int kb = ks * 8;
            uint32_t bf[8][2];
            #pragma unroll
            for (int ni = 0; ni < 8; ni++) {
                const int n = wn + ni*8 + fr;
                const int xn = (n & 7) << 2;
                bf[ni][0] = __float_as_uint(B_s[n*32 + ((kb + fc)     ^ xn)]);
                bf[ni][1] = __float_as_uint(B_s[n*32 + ((kb + fc + 4) ^ xn)]);
            }
            #pragma unroll
            for (int mi = 0; mi < 4; mi++) {
                const int m  = wm + mi*16 + fr;
                const int m2 = m + 8;
                const int xm  = (m  & 7) << 2;
                const int xm2 = (m2 & 7) << 2;
                uint32_t af[4];
                af[0] = __float_as_uint(A_s[m *32 + ((kb + fc)     ^ xm )]);
                af[1] = __float_as_uint(A_s[m2*32 + ((kb + fc)     ^ xm2)]);
                af[2] = __float_as_uint(A_s[m *32 + ((kb + fc + 4) ^ xm )]);
                af[3] = __float_as_uint(A_s[m2*32 + ((kb + fc + 4) ^ xm2)]);
                #pragma unroll
                for (int ni = 0; ni < 8; ni++)
                    mma_tf32(acc[mi][ni], af, bf[ni]);
            }
        }
        __syncthreads();
    }
    #undef G_LOAD

    // epilogue
    #pragma unroll
    for (int mi = 0; mi < 4; mi++) {
        const int r0 = m0 + wm + mi*16 + fr;
        #pragma unroll
        for (int ni = 0; ni < 8; ni++) {
            const int col = n0 + wn + ni*8 + fc*2;
            float v0 = acc[mi][ni][0], v1 = acc[mi][ni][1];
            float v2 = acc[mi][ni][2], v3 = acc[mi][ni][3];
            if (BIAS) {
                const float b0 = __ldg(bias + col), b1 = __ldg(bias + col + 1);
                v0 += b0; v1 += b1; v2 += b0; v3 += b1;
            }
            if (ROUND) { v0 = rtf32(v0); v1 = rtf32(v1); v2 = rtf32(v2); v3 = rtf32(v3); }
            *(float2*)(C + (size_t)r0       * Cc + col) = make_float2(v0, v1);
            *(float2*)(C + (size_t)(r0 + 8) * Cc + col) = make_float2(v2, v3);
        }
    }
}

__global__ void __launch_bounds__(256, 1)
gemm_tc_bias(const float* __restrict__ A, const float* __restrict__ W,
             const float* __restrict__ bias, float* __restrict__ C) {
    gemm_body<true, false>(A, W, bias, C);
}

// QKV fused: blockIdx.z selects projection; outputs RN-rounded to tf32
__global__ void __launch_bounds__(256, 1)
gemm_tc_qkv(const float* __restrict__ A,
            const float* __restrict__ W0, const float* __restrict__ W1,
            const float* __restrict__ W2,
            float* __restrict__ C0, float* __restrict__ C1, float* __restrict__ C2) {
    const float* W = (blockIdx.z == 0) ? W0 : (blockIdx.z == 1) ? W1 : W2;
    float*       C = (blockIdx.z == 0) ? C0 : (blockIdx.z == 1) ? C1 : C2;
    gemm_body<false, true>(A, W, nullptr, C);
}

// ===========================================================================
// Flash-attention, tf32 mma.sync. CTA = 128 threads (4 warps), one
// (b, h, 64-query tile). Q fragments register-resident. Ps aliases Qs.
// smem 102400B -> 2 CTAs/SM.
// ===========================================================================
#define A_QS  0
#define A_KS  (64*132)
#define A_VT  (2*64*132)
#define A_SMEMF (2*64*132 + 128*68)
#define A_SMEMB (A_SMEMF*4)   // 102400

__global__ void __launch_bounds__(128) attn_mma(const int* __restrict__ pm)
{
    extern __shared__ float sm[];
    float* Qs = sm + A_QS;   // [64][132]; later reused as Ps [64][68]
    float* Ks = sm + A_KS;   // [64][132]
    float* Vt = sm + A_VT;   // [128][68]
    float* Ps = Qs;
    const uint32_t qsb = smem_u32(Qs);
    const uint32_t ksb = smem_u32(Ks);

    const int qb = blockIdx.x;
    const int h  = blockIdx.y;
    const int b  = blockIdx.z;
    const int tid  = threadIdx.x;
    const int lane = tid & 31;
    const int warp = tid >> 5;
    const int fr = lane >> 2;
    const int fc = lane & 3;

    const size_t hoff = (size_t)h * Dd;
    const float* Qg = g_q + (size_t)b * Tt * Cc + hoff;
    const float* Kg = g_k + (size_t)b * Tt * Cc + hoff;
    const float* Vg = g_v + (size_t)b * Tt * Cc + hoff;
    const int q0 = qb * 64;

    // ---- load Q tile [64][128] into Qs (stride 132) ----
    #pragma unroll
    for (int i = 0; i < 16; i++) {
        const int id = i*128 + tid;
        const int r = id >> 5, ch = id & 31;
        cp_async16(qsb + (r*132 + ch*4)*4, Qg + (size_t)(q0 + r)*Cc + ch*4);
    }
    cp_commit(); cp_wait0();
    __syncthreads();

    // ---- Q fragments (scaled, RN-rounded), register-resident ----
    const float scale = 0.08838834764831845f;   // 1/sqrt(128)
    uint32_t qf[16][4];
    {
        const int m = warp*16 + fr;
        #pragma unroll
        for (int kb = 0; kb < 16; kb++) {
            const int k0 = kb*8;
            qf[kb][0] = rtf32u(Qs[m     *132 + k0 + fc    ] * scale);
            qf[kb][1] = rtf32u(Qs[(m+8) *132 + k0 + fc    ] * scale);
            qf[kb][2] = rtf32u(Qs[m     *132 + k0 + fc + 4] * scale);
            qf[kb][3] = rtf32u(Qs[(m+8) *132 + k0 + fc + 4] * scale);
        }
    }

    const int rowA = q0 + warp*16 + fr;
    const int rowB = rowA + 8;
    const int pmA = pm[b*Tt + rowA];
    const int pmB = pm[b*Tt + rowB];

    float o[16][4];
    #pragma unroll
    for (int i = 0; i < 16; i++)
        #pragma unroll
        for (int j = 0; j < 4; j++) o[i][j] = 0.f;
    float mA = -INFINITY, mB = -INFINITY, lA = 0.f, lB = 0.f;

    for (int kt = 0; kt <= qb; kt++) {
        __syncthreads();   // prev tile done reading Ks/Vt/Ps (and Q frags built)

        // K tile -> Ks (cp.async), V tile -> Vt transposed (ld+sts)
        #pragma unroll
        for (int i = 0; i < 16; i++) {
            const int id = i*128 + tid;
            const int r = id >> 5, ch = id & 31;
            cp_async16(ksb + (r*132 + ch*4)*4, Kg + (size_t)(kt*64 + r)*Cc + ch*4);
        }
        cp_commit();
        #pragma unroll
        for (int i = 0; i < 16; i++) {
            const int id = i*128 + tid;
            const int s = id >> 5, d0 = (id & 31) * 4;
            float4 v4 = *(const float4*)(Vg + (size_t)(kt*64 + s)*Cc + d0);
            Vt[(d0+0)*68 + s] = v4.x;
            Vt[(d0+1)*68 + s] = v4.y;
            Vt[(d0+2)*68 + s] = v4.z;
            Vt[(d0+3)*68 + s] = v4.w;
        }
        cp_wait0();
        __syncthreads();

        // ---- S = Q K^T ----
        float sa[8][4];
        #pragma unroll
        for (int ni = 0; ni < 8; ni++)
            #pragma unroll
            for (int j = 0; j < 4; j++) sa[ni][j] = 0.f;

        #pragma unroll
        for (int kb = 0; kb < 16; kb++) {
            const int k0 = kb*8;
            #pragma unroll
            for (int ni = 0; ni < 8; ni++) {
                uint32_t bf[2];
                bf[0] = __float_as_uint(Ks[(ni*8 + fr)*132 + k0 + fc    ]);
                bf[1] = __float_as_uint(Ks[(ni*8 + fr)*132 + k0 + fc + 4]);
                mma_tf32(sa[ni], qf[kb], bf);
            }
        }

        // ---- mask + online softmax ----
        float mxA = -INFINITY, mxB = -INFINITY;
        #pragma unroll
        for (int ni = 0; ni < 8; ni++) {
            const int c0 = kt*64 + ni*8 + 2*fc;
            float s0 = sa[ni][0], s1 = sa[ni][1], s2 = sa[ni][2], s3 = sa[ni][3];
            if (pmA == 0) { s0 = -1e9f; s1 = -1e9f; }
            if (pmB == 0) { s2 = -1e9f; s3 = -1e9f; }
            if (kt == qb) {
                if (c0     > rowA) s0 = -INFINITY;
                if (c0 + 1 > rowA) s1 = -INFINITY;
                if (c0     > rowB) s2 = -INFINITY;
                if (c0 + 1 > rowB) s3 = -INFINITY;
            }
            sa[ni][0] = s0; sa[ni][1] = s1; sa[ni][2] = s2; sa[ni][3] = s3;
            mxA = fmaxf(mxA, fmaxf(s0, s1));
            mxB = fmaxf(mxB, fmaxf(s2, s3));
        }
        mxA = fmaxf(mxA, __shfl_xor_sync(0xffffffffu, mxA, 1));
        mxA = fmaxf(mxA, __shfl_xor_sync(0xffffffffu, mxA, 2));
        mxB = fmaxf(mxB, __shfl_xor_sync(0xffffffffu, mxB, 1));
        mxB = fmaxf(mxB, __shfl_xor_sync(0xffffffffu, mxB, 2));

        const float mnA = fmaxf(mA, mxA), mnB = fmaxf(mB, mxB);
        const float sfA = __expf(mA - mnA), sfB = __expf(mB - mnB);
        mA = mnA; mB = mnB;

        float suA = 0.f, suB = 0.f;
        #pragma unroll
        for (int ni = 0; ni < 8; ni++) {
            float p0 = rtf32(__expf(sa[ni][0] - mA));
            float p1 = rtf32(__expf(sa[ni][1] - mA));
            float p2 = rtf32(__expf(sa[ni][2] - mB));
            float p3 = rtf32(__expf(sa[ni][3] - mB));
            suA += p0 + p1; suB += p2 + p3;
            const int sc = ni*8 + 2*fc;
            *(float2*)&Ps[(warp*16 + fr    )*68 + sc] = make_float2(p0, p1);
            *(float2*)&Ps[(warp*16 + fr + 8)*68 + sc] = make_float2(p2, p3);
        }
        suA += __shfl_xor_sync(0xffffffffu, suA, 1);
        suA += __shfl_xor_sync(0xffffffffu, suA, 2);
        suB += __shfl_xor_sync(0xffffffffu, suB, 1);
        suB += __shfl_xor_sync(0xffffffffu, suB, 2);
        lA = lA*sfA + suA;
        lB = lB*sfB + suB;
        #pragma unroll
        for (int ni = 0; ni < 16; ni++) {
            o[ni][0] *= sfA; o[ni][1] *= sfA;
            o[ni][2] *= sfB; o[ni][3] *= sfB;
        }
        __syncthreads();   // Ps complete before PV reads

        // ---- O += P V ----
        #pragma unroll
        for (int kb = 0; kb < 8; kb++) {
            const int k0 = kb*8;
            uint32_t af[4];
            af[0] = __float_as_uint(Ps[(warp*16 + fr    )*68 + k0 + fc    ]);
            af[1] = __float_as_uint(Ps[(warp*16 + fr + 8)*68 + k0 + fc    ]);
            af[2] = __float_as_uint(Ps[(warp*16 + fr    )*68 + k0 + fc + 4]);
            af[3] = __float_as_uint(Ps[(warp*16 + fr + 8)*68 + k0 + fc + 4]);
            #pragma unroll
            for (int ni = 0; ni < 16; ni++) {
                uint32_t bf[2];
                bf[0] = __float_as_uint(Vt[(ni*8 + fr)*68 + k0 + fc    ]);
                bf[1] = __float_as_uint(Vt[(ni*8 + fr)*68 + k0 + fc + 4]);
                mma_tf32(o[ni], af, bf);
            }
        }
    }

    // ---- epilogue: ctx = O / l, RN-rounded to tf32 for the proj GEMM ----
    const float iA = 1.f / lA, iB = 1.f / lB;
    float* cpA = g_ctx + (size_t)(b*Tt + rowA)*Cc + hoff;
    float* cpB = g_ctx + (size_t)(b*Tt + rowB)*Cc + hoff;
    #pragma unroll
    for (int ni = 0; ni < 16; ni++) {
        const int d0 = ni*8 + 2*fc;
        *(float2*)(cpA + d0) = make_float2(rtf32(o[ni][0]*iA), rtf32(o[ni][1]*iA));
        *(float2*)(cpB + d0) = make_float2(rtf32(o[ni][2]*iB), rtf32(o[ni][3]*iB));
    }
}

// ===========================================================================
extern "C" void kernel_launch(void* const* d_in, const int* in_sizes, int n_in,
                              void* d_out, int out_size)
{
    (void)in_sizes; (void)n_in; (void)out_size;
    const float* x  = (const float*)d_in[0];
    const int*   pm = (const int*)  d_in[1];
    const float* Wq = (const float*)d_in[2];
    const float* Wk = (const float*)d_in[3];
    const float* Wv = (const float*)d_in[4];
    const float* Wp = (const float*)d_in[5];
    const float* bp = (const float*)d_in[6];
    float* out = (float*)d_out;

    float *q, *k, *v, *ctx, *xr, *wq, *wk, *wv, *wp;
    cudaGetSymbolAddress((void**)&q,   g_q);
    cudaGetSymbolAddress((void**)&k,   g_k);
    cudaGetSymbolAddress((void**)&v,   g_v);
    cudaGetSymbolAddress((void**)&ctx, g_ctx);
    cudaGetSymbolAddress((void**)&xr,  g_xr);
    cudaGetSymbolAddress((void**)&wq,  g_wq);
    cudaGetSymbolAddress((void**)&wk,  g_wk);
    cudaGetSymbolAddress((void**)&wv,  g_wv);
    cudaGetSymbolAddress((void**)&wp,  g_wp);

    // Pre-round all MMA source operands to tf32 (RN), one fused launch
    const int nb = (NTOK*Cc/4 + 255) / 256;   // largest buffer (x)
    round_tf32_all<<<dim3(nb, 1, 5), 256>>>(
        (const float4*)x,  (float4*)xr,
        (const float4*)Wq, (float4*)wq,
        (const float4*)Wk, (float4*)wk,
        (const float4*)Wv, (float4*)wv,
        (const float4*)Wp, (float4*)wp);

    cudaFuncSetAttribute(gemm_tc_qkv,  cudaFuncAttributeMaxDynamicSharedMemorySize, G_SMEM);
    cudaFuncSetAttribute(gemm_tc_bias, cudaFuncAttributeMaxDynamicSharedMemorySize, G_SMEM);
    cudaFuncSetAttribute(attn_mma,     cudaFuncAttributeMaxDynamicSharedMemorySize, A_SMEMB);

    // QKV projections (fused launch), outputs RN-rounded tf32
    gemm_tc_qkv<<<dim3(Cc/256, NTOK/128, 3), 256, G_SMEM>>>(xr, wq, wk, wv, q, k, v);

    // attention (tensor-core flash)
    attn_mma<<<dim3(Tt/64, Hh, Bb), 128, A_SMEMB>>>(pm);

    // output projection + bias
    gemm_tc_bias<<<dim3(Cc/256, NTOK/128), 256, G_SMEM>>>(ctx, wp, bp, out);
}

// round 7
// speedup vs baseline: 1.0237x; 1.0237x over previous
#include <cuda_runtime.h>
#include <cstdint>
#include <math.h>

#define Bb 2
#define Tt 2048
#define Cc 2048
#define Hh 16
#define Dd 128
#define NTOK (Bb*Tt)   // 4096

// Scratch (device globals: no runtime allocation allowed)
__device__ float g_q[(size_t)NTOK*Cc];
__device__ float g_k[(size_t)NTOK*Cc];
__device__ float g_v[(size_t)NTOK*Cc];
__device__ float g_ctx[(size_t)NTOK*Cc];
__device__ float g_xr[(size_t)NTOK*Cc];
__device__ float g_wq[(size_t)Cc*Cc];
__device__ float g_wk[(size_t)Cc*Cc];
__device__ float g_wv[(size_t)Cc*Cc];
__device__ float g_wp[(size_t)Cc*Cc];

// ===========================================================================
// helpers
// ===========================================================================
__device__ __forceinline__ uint32_t smem_u32(const void* p) {
    uint32_t a;
    asm("{ .reg .u64 t; cvta.to.shared.u64 t, %1; cvt.u32.u64 %0, t; }" : "=r"(a) : "l"(p));
    return a;
}
__device__ __forceinline__ void cp_async16(uint32_t dst, const void* src) {
    asm volatile("cp.async.cg.shared.global [%0], [%1], 16;" :: "r"(dst), "l"(src) : "memory");
}
__device__ __forceinline__ void cp_commit() {
    asm volatile("cp.async.commit_group;" ::: "memory");
}
__device__ __forceinline__ void cp_wait1() {
    asm volatile("cp.async.wait_group 1;" ::: "memory");
}
__device__ __forceinline__ void cp_wait0() {
    asm volatile("cp.async.wait_group 0;" ::: "memory");
}
__device__ __forceinline__ float rtf32(float x) {
    uint32_t o;
    asm("cvt.rna.tf32.f32 %0, %1;" : "=r"(o) : "f"(x));
    return __uint_as_float(o);
}
// ldmatrix x4: 4 8x8 b16 matrices (= 4 8x4 tf32 tiles); addr supplied per lane
__device__ __forceinline__ void ldsm_x4(uint32_t* r, uint32_t addr) {
    asm volatile("ldmatrix.sync.aligned.m8n8.x4.shared.b16 {%0,%1,%2,%3}, [%4];"
                 : "=r"(r[0]), "=r"(r[1]), "=r"(r[2]), "=r"(r[3]) : "r"(addr));
}
// m16n8k8 TF32 MMA, fp32 accumulate
__device__ __forceinline__ void mma_tf32(float* c, const uint32_t* a, const uint32_t* b) {
    asm volatile(
        "mma.sync.aligned.m16n8k8.row.col.f32.tf32.tf32.f32 "
        "{%0,%1,%2,%3}, {%4,%5,%6,%7}, {%8,%9}, {%0,%1,%2,%3};"
        : "+f"(c[0]), "+f"(c[1]), "+f"(c[2]), "+f"(c[3])
        : "r"(a[0]), "r"(a[1]), "r"(a[2]), "r"(a[3]), "r"(b[0]), "r"(b[1]));
}

// ===========================================================================
// Fused round-to-TF32 preprocessing (z selects buffer)
// ===========================================================================
__global__ void __launch_bounds__(256) round_tf32_all(
    const float4* __restrict__ x,  float4* __restrict__ xr,
    const float4* __restrict__ w0, float4* __restrict__ r0,
    const float4* __restrict__ w1, float4* __restrict__ r1,
    const float4* __restrict__ w2, float4* __restrict__ r2,
    const float4* __restrict__ w3, float4* __restrict__ r3)
{
    const int z = blockIdx.z;
    const float4* src; float4* dst; int n4;
    if      (z == 0) { src = x;  dst = xr; n4 = NTOK*Cc/4; }
    else if (z == 1) { src = w0; dst = r0; n4 = Cc*Cc/4; }
    else if (z == 2) { src = w1; dst = r1; n4 = Cc*Cc/4; }
    else if (z == 3) { src = w2; dst = r2; n4 = Cc*Cc/4; }
    else             { src = w3; dst = r3; n4 = Cc*Cc/4; }
    int i = blockIdx.x * blockDim.x + threadIdx.x;
    if (i < n4) {
        float4 v = src[i];
        v.x = rtf32(v.x); v.y = rtf32(v.y); v.z = rtf32(v.z); v.w = rtf32(v.w);
        dst[i] = v;
    }
}

// ===========================================================================
// TF32 mma.sync GEMM: C[m,n] = sum_k A[m,k]*W[n,k] (+ bias[n])
// CTA 128x256, 8 warps, warp tile 64x64, BK=32, 3-stage cp.async.
// ldmatrix fragment loads + register double-buffering. One barrier/stage.
// ===========================================================================
#define G_BK     32
#define G_STAGES 3
#define G_ATSZ   (128*G_BK)
#define G_BTSZ   (256*G_BK)
#define G_SMEM   (G_STAGES*(G_ATSZ+G_BTSZ)*4)   // 147456 bytes
#define G_NSTEP  (Cc / G_BK)                    // 64

template<bool BIAS, bool ROUND>
__device__ __forceinline__ void gemm_body(const float* __restrict__ A,
                                          const float* __restrict__ W,
                                          const float* __restrict__ bias,
                                          float* __restrict__ C)
{
    extern __shared__ float sm[];
    float* As = sm;
    float* Bs = sm + G_STAGES * G_ATSZ;
    const uint32_t asb = smem_u32(As);
    const uint32_t bsb = smem_u32(Bs);

    const int tid  = threadIdx.x;
    const int lane = tid & 31;
    const int warp = tid >> 5;
    const int n0 = blockIdx.x * 256;
    const int m0 = blockIdx.y * 128;
    const int wm = (warp & 1) * 64;
    const int wn = (warp >> 1) * 64;
    const int fr = lane >> 2;
    const int fc = lane & 3;

    // ---- ldmatrix per-lane addressing ----
    // A x4 matrices per mi: (m,k0),(m+8,k0),(m,k4),(m+8,k4)
    const int a_msel = (lane >> 3) & 1;
    const int a_ksel = lane >> 4;
    uint32_t a_off[4], a_sw[4];
    #pragma unroll
    for (int mi = 0; mi < 4; mi++) {
        const int r = wm + mi*16 + a_msel*8 + (lane & 7);
        a_off[mi] = (uint32_t)r * 128;           // bytes (row stride 32 floats)
        a_sw[mi]  = (uint32_t)(r & 7);
    }
    // B x4 matrices per pair pi: (n0,k0),(n0,k4),(n1,k0),(n1,k4)  [ni=2pi,2pi+1]
    const int b_nsel = (lane >> 4) & 1;
    const int b_ksel = (lane >> 3) & 1;
    uint32_t b_off[4], b_sw[4];
    #pragma unroll
    for (int pi = 0; pi < 4; pi++) {
        const int n = wn + pi*16 + b_nsel*8 + (lane & 7);
        b_off[pi] = (uint32_t)n * 128;
        b_sw[pi]  = (uint32_t)(n & 7);
    }

    // loaders
    const int lrA = tid >> 1;
    const int ljA = (tid & 1) * 4;
    const float* Ag = A + (size_t)(m0 + lrA) * Cc;
    const float* Wg = W + (size_t)(n0 + tid) * Cc;
    const uint32_t swA = (uint32_t)(lrA & 7);
    const uint32_t swB = (uint32_t)(tid & 7);

    float acc[4][8][4];
    #pragma unroll
    for (int i = 0; i < 4; i++)
        #pragma unroll
        for (int j = 0; j < 8; j++)
            #pragma unroll
            for (int q = 0; q < 4; q++) acc[i][j][q] = 0.f;

    #define G_LOAD(s, st) do {                                                  \
        const uint32_t sa = asb + (st) * (G_ATSZ*4);                             \
        const uint32_t sb = bsb + (st) * (G_BTSZ*4);                             \
        const int kof = (s) * G_BK;                                              \
        _Pragma("unroll")                                                        \
        for (int j = 0; j < 4; j++) {                                            \
            const int ch = ljA + j;                                              \
            cp_async16(sa + (lrA*32 + (((uint32_t)ch ^ swA) << 2)) * 4,          \
                       Ag + kof + ch*4);                                         \
        }                                                                        \
        _Pragma("unroll")                                                        \
        for (int j = 0; j < 8; j++) {                                            \
            cp_async16(sb + (tid*32 + (((uint32_t)j ^ swB) << 2)) * 4,           \
                       Wg + kof + j*4);                                          \
        }                                                                        \
    } while (0)

    #define G_FRAG(buf, Ab, Bb_, ks) do {                                        \
        const uint32_t ka = (uint32_t)(2*(ks) + a_ksel);                         \
        const uint32_t kb_ = (uint32_t)(2*(ks) + b_ksel);                        \
        _Pragma("unroll")                                                        \
        for (int mi = 0; mi < 4; mi++)                                           \
            ldsm_x4(af[buf][mi], (Ab) + a_off[mi] + ((ka ^ a_sw[mi]) << 4));     \
        _Pragma("unroll")                                                        \
        for (int pi = 0; pi < 4; pi++)                                           \
            ldsm_x4(bfr[buf][pi], (Bb_) + b_off[pi] + ((kb_ ^ b_sw[pi]) << 4));  \
    } while (0)

    G_LOAD(0, 0); cp_commit();
    G_LOAD(1, 1); cp_commit();

    uint32_t af[2][4][4], bfr[2][4][4];

    for (int s = 0; s < G_NSTEP; s++) {
        cp_wait1();
        __syncthreads();
        if (s + 2 < G_NSTEP) { G_LOAD(s + 2, (s + 2) % G_STAGES); }
        cp_commit();

        const uint32_t A_sa = asb + (s % G_STAGES) * (G_ATSZ*4);
        const uint32_t B_sa = bsb + (s % G_STAGES) * (G_BTSZ*4);

        G_FRAG(0, A_sa, B_sa, 0);
        #pragma unroll
        for (int ks = 0; ks < 4; ks++) {
            const int cur = ks & 1;
            if (ks < 3) G_FRAG(cur ^ 1, A_sa, B_sa, ks + 1);
            #pragma unroll
            for (int mi = 0; mi < 4; mi++)
                #pragma unroll
                for (int ni = 0; ni < 8; ni++)
                    mma_tf32(acc[mi][ni], af[cur][mi], &bfr[cur][ni >> 1][(ni & 1) * 2]);
        }
        // single barrier per stage (at loop top) is sufficient:
        // next iteration's loads (into stage s%3) are program-ordered after it.
    }
    #undef G_LOAD
    #undef G_FRAG
    __syncthreads();

    // epilogue
    #pragma unroll
    for (int mi = 0; mi < 4; mi++) {
        const int r0 = m0 + wm + mi*16 + fr;
        #pragma unroll
        for (int ni = 0; ni < 8; ni++) {
            const int col = n0 + wn + ni*8 + fc*2;
            float v0 = acc[mi][ni][0], v1 = acc[mi][ni][1];
            float v2 = acc[mi][ni][2], v3 = acc[mi][ni][3];
            if (BIAS) {
                const float b0 = __ldg(bias + col), b1 = __ldg(bias + col + 1);
                v0 += b0; v1 += b1; v2 += b0; v3 += b1;
            }
            if (ROUND) { v0 = rtf32(v0); v1 = rtf32(v1); v2 = rtf32(v2); v3 = rtf32(v3); }
            *(float2*)(C + (size_t)r0       * Cc + col) = make_float2(v0, v1);
            *(float2*)(C + (size_t)(r0 + 8) * Cc + col) = make_float2(v2, v3);
        }
    }
}

__global__ void __launch_bounds__(256, 1)
gemm_tc_bias(const float* __restrict__ A, const float* __restrict__ W,
             const float* __restrict__ bias, float* __restrict__ C) {
    gemm_body<true, false>(A, W, bias, C);
}

__global__ void __launch_bounds__(256, 1)
gemm_tc_qkv(const float* __restrict__ A,
            const float* __restrict__ W0, const float* __restrict__ W1,
            const float* __restrict__ W2,
            float* __restrict__ C0, float* __restrict__ C1, float* __restrict__ C2) {
    const float* W = (blockIdx.z == 0) ? W0 : (blockIdx.z == 1) ? W1 : W2;
    float*       C = (blockIdx.z == 0) ? C0 : (blockIdx.z == 1) ? C1 : C2;
    gemm_body<false, true>(A, W, nullptr, C);
}

// ===========================================================================
// Flash-attention, tf32 mma.sync + ldmatrix. CTA = 128 threads, one
// (b, h, 64-query tile). Q frags register-resident (raw; scale applied to S).
// Ps aliases Qs. smem 102400B -> 2 CTAs/SM.
// ===========================================================================
#define A_QS  0
#define A_KS  (64*132)
#define A_VT  (2*64*132)
#define A_SMEMF (2*64*132 + 128*68)
#define A_SMEMB (A_SMEMF*4)

__global__ void __launch_bounds__(128) attn_mma(const int* __restrict__ pm)
{
    extern __shared__ float sm[];
    float* Qs = sm + A_QS;   // [64][132]; reused as Ps [64][68]
    float* Ks = sm + A_KS;   // [64][132]
    float* Vt = sm + A_VT;   // [128][68]
    float* Ps = Qs;
    const uint32_t qsb = smem_u32(Qs);
    const uint32_t ksb = smem_u32(Ks);
    const uint32_t vtb = smem_u32(Vt);
    const uint32_t psb = qsb;

    const int qb = blockIdx.x;
    const int h  = blockIdx.y;
    const int b  = blockIdx.z;
    const int tid  = threadIdx.x;
    const int lane = tid & 31;
    const int warp = tid >> 5;
    const int fr = lane >> 2;
    const int fc = lane & 3;

    // ldmatrix lane roles (A-style and B-style)
    const int a_msel = (lane >> 3) & 1;
    const int a_ksel = lane >> 4;
    const int b_nsel = (lane >> 4) & 1;
    const int b_ksel = (lane >> 3) & 1;
    const int a_row  = warp*16 + a_msel*8 + (lane & 7);

    const size_t hoff = (size_t)h * Dd;
    const float* Qg = g_q + (size_t)b * Tt * Cc + hoff;
    const float* Kg = g_k + (size_t)b * Tt * Cc + hoff;
    const float* Vg = g_v + (size_t)b * Tt * Cc + hoff;
    const int q0 = qb * 64;

    // ---- load Q tile [64][128] into Qs (stride 132) ----
    #pragma unroll
    for (int i = 0; i < 16; i++) {
        const int id = i*128 + tid;
        const int r = id >> 5, ch = id & 31;
        cp_async16(qsb + (r*132 + ch*4)*4, Qg + (size_t)(q0 + r)*Cc + ch*4);
    }
    cp_commit(); cp_wait0();
    __syncthreads();

    // ---- Q fragments (raw bits), register-resident ----
    uint32_t qf[16][4];
    #pragma unroll
    for (int kb = 0; kb < 16; kb++)
        ldsm_x4(qf[kb], qsb + (a_row*132 + kb*8 + a_ksel*4)*4);
    __syncthreads();   // Qs reads done before Ps (aliased) writes

    const float scale = 0.08838834764831845f;   // applied to S after MMA
    const int rowA = q0 + warp*16 + fr;
    const int rowB = rowA + 8;
    const int pmA = pm[b*Tt + rowA];
    const int pmB = pm[b*Tt + rowB];

    float o[16][4];
    #pragma unroll
    for (int i = 0; i < 16; i++)
        #pragma unroll
        for (int j = 0; j < 4; j++) o[i][j] = 0.f;
    float mA = -INFINITY, mB = -INFINITY, lA = 0.f, lB = 0.f;

    for (int kt = 0; kt <= qb; kt++) {
        __syncthreads();   // prev tile done reading Ks/Vt/Ps

        #pragma unroll
        for (int i = 0; i < 16; i++) {
            const int id = i*128 + tid;
            const int r = id >> 5, ch = id & 31;
            cp_async16(ksb + (r*132 + ch*4)*4, Kg + (size_t)(kt*64 + r)*Cc + ch*4);
        }
        cp_commit();
        #pragma unroll
        for (int i = 0; i < 16; i++) {
            const int id = i*128 + tid;
            const int s = id >> 5, d0 = (id & 31) * 4;
            float4 v4 = *(const float4*)(Vg + (size_t)(kt*64 + s)*Cc + d0);
            Vt[(d0+0)*68 + s] = v4.x;
            Vt[(d0+1)*68 + s] = v4.y;
            Vt[(d0+2)*68 + s] = v4.z;
            Vt[(d0+3)*68 + s] = v4.w;
        }
        cp_wait0();
        __syncthreads();

        // ---- S = Q K^T (ldmatrix B frags from Ks) ----
        float sa[8][4];
        #pragma unroll
        for (int ni = 0; ni < 8; ni++)
            #pragma unroll
            for (int j = 0; j < 4; j++) sa[ni][j] = 0.f;

        #pragma unroll
        for (int kb = 0; kb < 16; kb++) {
            uint32_t bq[4][4];
            #pragma unroll
            for (int pi = 0; pi < 4; pi++) {
                const int n = pi*16 + b_nsel*8 + (lane & 7);
                ldsm_x4(bq[pi], ksb + (n*132 + kb*8 + b_ksel*4)*4);
            }
            #pragma unroll
            for (int ni = 0; ni < 8; ni++)
                mma_tf32(sa[ni], qf[kb], &bq[ni >> 1][(ni & 1) * 2]);
        }

        // ---- mask + online softmax (scale folded in here) ----
        float mxA = -INFINITY, mxB = -INFINITY;
        #pragma unroll
        for (int ni = 0; ni < 8; ni++) {
            const int c0 = kt*64 + ni*8 + 2*fc;
            float s0 = sa[ni][0]*scale, s1 = sa[ni][1]*scale;
            float s2 = sa[ni][2]*scale, s3 = sa[ni][3]*scale;
            if (pmA == 0) { s0 = -1e9f; s1 = -1e9f; }
            if (pmB == 0) { s2 = -1e9f; s3 = -1e9f; }
            if (kt == qb) {
                if (c0     > rowA) s0 = -INFINITY;
                if (c0 + 1 > rowA) s1 = -INFINITY;
                if (c0     > rowB) s2 = -INFINITY;
                if (c0 + 1 > rowB) s3 = -INFINITY;
            }
            sa[ni][0] = s0; sa[ni][1] = s1; sa[ni][2] = s2; sa[ni][3] = s3;
            mxA = fmaxf(mxA, fmaxf(s0, s1));
            mxB = fmaxf(mxB, fmaxf(s2, s3));
        }
        mxA = fmaxf(mxA, __shfl_xor_sync(0xffffffffu, mxA, 1));
        mxA = fmaxf(mxA, __shfl_xor_sync(0xffffffffu, mxA, 2));
        mxB = fmaxf(mxB, __shfl_xor_sync(0xffffffffu, mxB, 1));
        mxB = fmaxf(mxB, __shfl_xor_sync(0xffffffffu, mxB, 2));

        const float mnA = fmaxf(mA, mxA), mnB = fmaxf(mB, mxB);
        const float sfA = __expf(mA - mnA), sfB = __expf(mB - mnB);
        mA = mnA; mB = mnB;

        float suA = 0.f, suB = 0.f;
        #pragma unroll
        for (int ni = 0; ni < 8; ni++) {
            float p0 = rtf32(__expf(sa[ni][0] - mA));
            float p1 = rtf32(__expf(sa[ni][1] - mA));
            float p2 = rtf32(__expf(sa[ni][2] - mB));
            float p3 = rtf32(__expf(sa[ni][3] - mB));
            suA += p0 + p1; suB += p2 + p3;
            const int sc = ni*8 + 2*fc;
            *(float2*)&Ps[(warp*16 + fr    )*68 + sc] = make_float2(p0, p1);
            *(float2*)&Ps[(warp*16 + fr + 8)*68 + sc] = make_float2(p2, p3);
        }
        suA += __shfl_xor_sync(0xffffffffu, suA, 1);
        suA += __shfl_xor_sync(0xffffffffu, suA, 2);
        suB += __shfl_xor_sync(0xffffffffu, suB, 1);
        suB += __shfl_xor_sync(0xffffffffu, suB, 2);
        lA = lA*sfA + suA;
        lB = lB*sfB + suB;
        #pragma unroll
        for (int ni = 0; ni < 16; ni++) {
            o[ni][0] *= sfA; o[ni][1] *= sfA;
            o[ni][2] *= sfB; o[ni][3] *= sfB;
        }
        __syncthreads();   // Ps complete before PV reads

        // ---- O += P V (ldmatrix frags) ----
        #pragma unroll
        for (int kb = 0; kb < 8; kb++) {
            uint32_t pa[4];
            ldsm_x4(pa, psb + (a_row*68 + kb*8 + a_ksel*4)*4);
            #pragma unroll
            for (int pi = 0; pi < 8; pi++) {
                uint32_t bv[4];
                const int d = pi*16 + b_nsel*8 + (lane & 7);
                ldsm_x4(bv, vtb + (d*68 + kb*8 + b_ksel*4)*4);
                mma_tf32(o[pi*2    ], pa, &bv[0]);
                mma_tf32(o[pi*2 + 1], pa, &bv[2]);
            }
        }
    }

    // ---- epilogue: ctx = O / l, RN-rounded to tf32 for the proj GEMM ----
    const float iA = 1.f / lA, iB = 1.f / lB;
    float* cpA = g_ctx + (size_t)(b*Tt + rowA)*Cc + hoff;
    float* cpB = g_ctx + (size_t)(b*Tt + rowB)*Cc + hoff;
    #pragma unroll
    for (int ni = 0; ni < 16; ni++) {
        const int d0 = ni*8 + 2*fc;
        *(float2*)(cpA + d0) = make_float2(rtf32(o[ni][0]*iA), rtf32(o[ni][1]*iA));
        *(float2*)(cpB + d0) = make_float2(rtf32(o[ni][2]*iB), rtf32(o[ni][3]*iB));
    }
}

// ===========================================================================
extern "C" void kernel_launch(void* const* d_in, const int* in_sizes, int n_in,
                              void* d_out, int out_size)
{
    (void)in_sizes; (void)n_in; (void)out_size;
    const float* x  = (const float*)d_in[0];
    const int*   pm = (const int*)  d_in[1];
    const float* Wq = (const float*)d_in[2];
    const float* Wk = (const float*)d_in[3];
    const float* Wv = (const float*)d_in[4];
    const float* Wp = (const float*)d_in[5];
    const float* bp = (const float*)d_in[6];
    float* out = (float*)d_out;

    float *q, *k, *v, *ctx, *xr, *wq, *wk, *wv, *wp;
    cudaGetSymbolAddress((void**)&q,   g_q);
    cudaGetSymbolAddress((void**)&k,   g_k);
    cudaGetSymbolAddress((void**)&v,   g_v);
    cudaGetSymbolAddress((void**)&ctx, g_ctx);
    cudaGetSymbolAddress((void**)&xr,  g_xr);
    cudaGetSymbolAddress((void**)&wq,  g_wq);
    cudaGetSymbolAddress((void**)&wk,  g_wk);
    cudaGetSymbolAddress((void**)&wv,  g_wv);
    cudaGetSymbolAddress((void**)&wp,  g_wp);

    const int nb = (NTOK*Cc/4 + 255) / 256;
    round_tf32_all<<<dim3(nb, 1, 5), 256>>>(
        (const float4*)x,  (float4*)xr,
        (const float4*)Wq, (float4*)wq,
        (const float4*)Wk, (float4*)wk,
        (const float4*)Wv, (float4*)wv,
        (const float4*)Wp, (float4*)wp);

    cudaFuncSetAttribute(gemm_tc_qkv,  cudaFuncAttributeMaxDynamicSharedMemorySize, G_SMEM);
    cudaFuncSetAttribute(gemm_tc_bias, cudaFuncAttributeMaxDynamicSharedMemorySize, G_SMEM);
    cudaFuncSetAttribute(attn_mma,     cudaFuncAttributeMaxDynamicSharedMemorySize, A_SMEMB);

    gemm_tc_qkv<<<dim3(Cc/256, NTOK/128, 3), 256, G_SMEM>>>(xr, wq, wk, wv, q, k, v);
    attn_mma<<<dim3(Tt/64, Hh, Bb), 128, A_SMEMB>>>(pm);
    gemm_tc_bias<<<dim3(Cc/256, NTOK/128), 256, G_SMEM>>>(ctx, wp, bp, out);
}

// round 8
// speedup vs baseline: 2.0106x; 1.9641x over previous
#include <cuda_runtime.h>
#include <cuda_fp16.h>
#include <cstdint>
#include <math.h>

#define Bb 2
#define Tt 2048
#define Cc 2048
#define Hh 16
#define Dd 128
#define NTOK (Bb*Tt)   // 4096

// Scratch (device globals: no runtime allocation allowed)
__device__ __half g_xh [(size_t)NTOK*Cc];
__device__ __half g_wqh[(size_t)Cc*Cc];
__device__ __half g_wkh[(size_t)Cc*Cc];
__device__ __half g_wvh[(size_t)Cc*Cc];
__device__ __half g_wph[(size_t)Cc*Cc];
__device__ __half g_qh [(size_t)NTOK*Cc];
__device__ __half g_kh [(size_t)NTOK*Cc];
__device__ __half g_vh [(size_t)NTOK*Cc];
__device__ __half g_ctxh[(size_t)NTOK*Cc];

// ===========================================================================
// helpers
// ===========================================================================
__device__ __forceinline__ uint32_t smem_u32(const void* p) {
    uint32_t a;
    asm("{ .reg .u64 t; cvta.to.shared.u64 t, %1; cvt.u32.u64 %0, t; }" : "=r"(a) : "l"(p));
    return a;
}
__device__ __forceinline__ void cp_async16(uint32_t dst, const void* src) {
    asm volatile("cp.async.cg.shared.global [%0], [%1], 16;" :: "r"(dst), "l"(src) : "memory");
}
__device__ __forceinline__ void cp_commit() {
    asm volatile("cp.async.commit_group;" ::: "memory");
}
__device__ __forceinline__ void cp_wait1() {
    asm volatile("cp.async.wait_group 1;" ::: "memory");
}
__device__ __forceinline__ void cp_wait0() {
    asm volatile("cp.async.wait_group 0;" ::: "memory");
}
__device__ __forceinline__ void ldsm_x4(uint32_t* r, uint32_t addr) {
    asm volatile("ldmatrix.sync.aligned.m8n8.x4.shared.b16 {%0,%1,%2,%3}, [%4];"
                 : "=r"(r[0]), "=r"(r[1]), "=r"(r[2]), "=r"(r[3]) : "r"(addr));
}
__device__ __forceinline__ void ldsm_x4_t(uint32_t* r, uint32_t addr) {
    asm volatile("ldmatrix.sync.aligned.m8n8.x4.trans.shared.b16 {%0,%1,%2,%3}, [%4];"
                 : "=r"(r[0]), "=r"(r[1]), "=r"(r[2]), "=r"(r[3]) : "r"(addr));
}
// m16n8k16 fp16 MMA, fp32 accumulate
__device__ __forceinline__ void mma_f16(float* c, const uint32_t* a, const uint32_t* b) {
    asm volatile(
        "mma.sync.aligned.m16n8k16.row.col.f32.f16.f16.f32 "
        "{%0,%1,%2,%3}, {%4,%5,%6,%7}, {%8,%9}, {%0,%1,%2,%3};"
        : "+f"(c[0]), "+f"(c[1]), "+f"(c[2]), "+f"(c[3])
        : "r"(a[0]), "r"(a[1]), "r"(a[2]), "r"(a[3]), "r"(b[0]), "r"(b[1]));
}

// ===========================================================================
// fp32 -> fp16 conversion (z selects buffer)
// ===========================================================================
__global__ void __launch_bounds__(256) tohalf_all(
    const float4* __restrict__ x,  __half* __restrict__ xr,
    const float4* __restrict__ w0, __half* __restrict__ r0,
    const float4* __restrict__ w1, __half* __restrict__ r1,
    const float4* __restrict__ w2, __half* __restrict__ r2,
    const float4* __restrict__ w3, __half* __restrict__ r3)
{
    const int z = blockIdx.z;
    const float4* src; __half* dst; int n4;
    if      (z == 0) { src = x;  dst = xr; n4 = NTOK*Cc/4; }
    else if (z == 1) { src = w0; dst = r0; n4 = Cc*Cc/4; }
    else if (z == 2) { src = w1; dst = r1; n4 = Cc*Cc/4; }
    else if (z == 3) { src = w2; dst = r2; n4 = Cc*Cc/4; }
    else             { src = w3; dst = r3; n4 = Cc*Cc/4; }
    int i = blockIdx.x * blockDim.x + threadIdx.x;
    if (i < n4) {
        float4 v = src[i];
        *(__half2*)(dst + (size_t)i*4)     = __floats2half2_rn(v.x, v.y);
        *(__half2*)(dst + (size_t)i*4 + 2) = __floats2half2_rn(v.z, v.w);
    }
}

// ===========================================================================
// fp16 mma.sync GEMM: C[m,n] = sum_k A[m,k]*W[n,k] (+ bias[n])
// CTA 128x256, 8 warps, warp tile 64x64, BK=64 halves (128B rows), 3 stages.
// ldmatrix frags + register double buffering.
// ===========================================================================
#define G_BK     64                            // halves
#define G_ABY    (128*128)                     // A stage bytes (16KB)
#define G_BBY    (256*128)                     // B stage bytes (32KB)
#define G_STAGES 3
#define G_SMEM   (G_STAGES*(G_ABY+G_BBY))      // 147456
#define G_NSTEP  (Cc / G_BK)                   // 32

template<bool HALF_OUT>
__device__ __forceinline__ void gemm_body(const __half* __restrict__ A,
                                          const __half* __restrict__ W,
                                          const float* __restrict__ bias,
                                          float* __restrict__ Cf,
                                          __half* __restrict__ Ch)
{
    extern __shared__ char smc[];
    const uint32_t asb = smem_u32(smc);
    const uint32_t bsb = asb + G_STAGES * G_ABY;

    const int tid  = threadIdx.x;
    const int lane = tid & 31;
    const int warp = tid >> 5;
    const int n0 = blockIdx.x * 256;
    const int m0 = blockIdx.y * 128;
    const int wm = (warp & 1) * 64;
    const int wn = (warp >> 1) * 64;
    const int fr = lane >> 2;
    const int fc = lane & 3;

    // ldmatrix lane addressing
    const int a_msel = (lane >> 3) & 1;
    const int a_ksel = lane >> 4;
    const int b_nsel = (lane >> 4) & 1;
    const int b_ksel = (lane >> 3) & 1;
    uint32_t a_off[4], a_sw[4], b_off[4], b_sw[4];
    #pragma unroll
    for (int mi = 0; mi < 4; mi++) {
        const int r = wm + mi*16 + a_msel*8 + (lane & 7);
        a_off[mi] = (uint32_t)r * 128;
        a_sw[mi]  = (uint32_t)(r & 7);
    }
    #pragma unroll
    for (int pi = 0; pi < 4; pi++) {
        const int n = wn + pi*16 + b_nsel*8 + (lane & 7);
        b_off[pi] = (uint32_t)n * 128;
        b_sw[pi]  = (uint32_t)(n & 7);
    }

    // loaders: A 128 rows x 8 chunks (2 thr/row); B 256 rows x 8 chunks (1 thr/row)
    const int lrA = tid >> 1;
    const int ljA = (tid & 1) * 4;
    const __half* Ag = A + (size_t)(m0 + lrA) * Cc;
    const __half* Wg = W + (size_t)(n0 + tid) * Cc;
    const uint32_t swA = (uint32_t)(lrA & 7);
    const uint32_t swB = (uint32_t)(tid & 7);

    float acc[4][8][4];
    #pragma unroll
    for (int i = 0; i < 4; i++)
        #pragma unroll
        for (int j = 0; j < 8; j++)
            #pragma unroll
            for (int q = 0; q < 4; q++) acc[i][j][q] = 0.f;

    #define G_LOAD(s, st) do {                                                  \
        const uint32_t sa = asb + (st) * G_ABY;                                  \
        const uint32_t sb = bsb + (st) * G_BBY;                                  \
        const int kof = (s) * G_BK;                                              \
        _Pragma("unroll")                                                        \
        for (int j = 0; j < 4; j++) {                                            \
            const int ch = ljA + j;                                              \
            cp_async16(sa + lrA*128 + (((uint32_t)ch ^ swA) << 4),               \
                       Ag + kof + ch*8);                                         \
        }                                                                        \
        _Pragma("unroll")                                                        \
        for (int j = 0; j < 8; j++) {                                            \
            cp_async16(sb + tid*128 + (((uint32_t)j ^ swB) << 4),                \
                       Wg + kof + j*8);                                          \
        }                                                                        \
    } while (0)

    #define G_FRAG(buf, Ab, Bb_, ks) do {                                        \
        const uint32_t ka  = (uint32_t)(2*(ks) + a_ksel);                        \
        const uint32_t kb_ = (uint32_t)(2*(ks) + b_ksel);                        \
        _Pragma("unroll")                                                        \
        for (int mi = 0; mi < 4; mi++)                                           \
            ldsm_x4(af[buf][mi], (Ab) + a_off[mi] + ((ka ^ a_sw[mi]) << 4));     \
        _Pragma("unroll")                                                        \
        for (int pi = 0; pi < 4; pi++)                                           \
            ldsm_x4(bfr[buf][pi], (Bb_) + b_off[pi] + ((kb_ ^ b_sw[pi]) << 4));  \
    } while (0)

    G_LOAD(0, 0); cp_commit();
    G_LOAD(1, 1); cp_commit();

    uint32_t af[2][4][4], bfr[2][4][4];

    for (int s = 0; s < G_NSTEP; s++) {
        cp_wait1();
        __syncthreads();
        if (s + 2 < G_NSTEP) { G_LOAD(s + 2, (s + 2) % G_STAGES); }
        cp_commit();

        const uint32_t A_sa = asb + (s % G_STAGES) * G_ABY;
        const uint32_t B_sa = bsb + (s % G_STAGES) * G_BBY;

        G_FRAG(0, A_sa, B_sa, 0);
        #pragma unroll
        for (int ks = 0; ks < 4; ks++) {
            const int cur = ks & 1;
            if (ks < 3) G_FRAG(cur ^ 1, A_sa, B_sa, ks + 1);
            #pragma unroll
            for (int mi = 0; mi < 4; mi++)
                #pragma unroll
                for (int ni = 0; ni < 8; ni++)
                    mma_f16(acc[mi][ni], af[cur][mi], &bfr[cur][ni >> 1][(ni & 1) * 2]);
        }
    }
    #undef G_LOAD
    #undef G_FRAG
    __syncthreads();

    // epilogue
    #pragma unroll
    for (int mi = 0; mi < 4; mi++) {
        const int r0 = m0 + wm + mi*16 + fr;
        #pragma unroll
        for (int ni = 0; ni < 8; ni++) {
            const int col = n0 + wn + ni*8 + fc*2;
            if (HALF_OUT) {
                *(__half2*)(Ch + (size_t)r0       * Cc + col) =
                    __floats2half2_rn(acc[mi][ni][0], acc[mi][ni][1]);
                *(__half2*)(Ch + (size_t)(r0 + 8) * Cc + col) =
                    __floats2half2_rn(acc[mi][ni][2], acc[mi][ni][3]);
            } else {
                const float b0 = __ldg(bias + col), b1 = __ldg(bias + col + 1);
                *(float2*)(Cf + (size_t)r0       * Cc + col) =
                    make_float2(acc[mi][ni][0] + b0, acc[mi][ni][1] + b1);
                *(float2*)(Cf + (size_t)(r0 + 8) * Cc + col) =
                    make_float2(acc[mi][ni][2] + b0, acc[mi][ni][3] + b1);
            }
        }
    }
}

__global__ void __launch_bounds__(256, 1)
gemm_out(const __half* __restrict__ A, const __half* __restrict__ W,
         const float* __restrict__ bias, float* __restrict__ C) {
    gemm_body<false>(A, W, bias, C, nullptr);
}

__global__ void __launch_bounds__(256, 1)
gemm_qkv(const __half* __restrict__ A,
         const __half* __restrict__ W0, const __half* __restrict__ W1,
         const __half* __restrict__ W2,
         __half* __restrict__ C0, __half* __restrict__ C1, __half* __restrict__ C2) {
    const __half* W = (blockIdx.z == 0) ? W0 : (blockIdx.z == 1) ? W1 : W2;
    __half*       C = (blockIdx.z == 0) ? C0 : (blockIdx.z == 1) ? C1 : C2;
    gemm_body<true>(A, W, nullptr, nullptr, C);
}

// ===========================================================================
// Flash-attention, fp16 mma.sync. CTA = 128 threads, one (b,h,64-query tile).
// Q/K/V rows 256B (128 halves, 16 chunks), P rows 128B. V via ldmatrix.trans.
// smem 56KB -> 3 CTAs/SM.
// ===========================================================================
#define AT_Q 0
#define AT_K 16384
#define AT_V 32768
#define AT_P 49152
#define AT_SMEM 57344

__global__ void __launch_bounds__(128, 3) attn_f16(const int* __restrict__ pm)
{
    extern __shared__ char smc[];
    const uint32_t sb  = smem_u32(smc);
    const uint32_t qsb = sb + AT_Q, ksb = sb + AT_K, vsb = sb + AT_V, psb = sb + AT_P;

    const int qb = blockIdx.x;
    const int h  = blockIdx.y;
    const int b  = blockIdx.z;
    const int tid  = threadIdx.x;
    const int lane = tid & 31;
    const int warp = tid >> 5;
    const int fr = lane >> 2;
    const int fc = lane & 3;

    const int a_msel = (lane >> 3) & 1;
    const int a_ksel = lane >> 4;
    const int b_nsel = (lane >> 4) & 1;
    const int b_ksel = (lane >> 3) & 1;
    const int v_ssel = (lane >> 3) & 1;
    const int v_dsel = (lane >> 4) & 1;
    const int a_row  = warp*16 + a_msel*8 + (lane & 7);   // 0..63

    const size_t hoff = (size_t)h * Dd;
    const __half* Qg = g_qh + (size_t)b * Tt * Cc + hoff;
    const __half* Kg = g_kh + (size_t)b * Tt * Cc + hoff;
    const __half* Vg = g_vh + (size_t)b * Tt * Cc + hoff;
    const int q0 = qb * 64;

    // loader indices: 64 rows x 16 chunks, 2 threads/row, 8 chunks each
    const int lrow = tid >> 1;
    const int lch0 = (tid & 1) * 8;
    const uint32_t lsw = (uint32_t)(lrow & 7);

    // ---- load Q tile ----
    #pragma unroll
    for (int j = 0; j < 8; j++) {
        const int ch = lch0 + j;
        cp_async16(qsb + lrow*256 + (((uint32_t)ch ^ lsw) << 4),
                   Qg + (size_t)(q0 + lrow)*Cc + ch*8);
    }
    cp_commit(); cp_wait0();
    __syncthreads();

    // ---- Q fragments, register-resident ----
    uint32_t qf[8][4];
    #pragma unroll
    for (int kb = 0; kb < 8; kb++)
        ldsm_x4(qf[kb], qsb + a_row*256 + (((uint32_t)(2*kb + a_ksel) ^ (uint32_t)(a_row & 7)) << 4));

    const float scale = 0.08838834764831845f;
    const int rowA = q0 + warp*16 + fr;
    const int rowB = rowA + 8;
    const int pmA = pm[b*Tt + rowA];
    const int pmB = pm[b*Tt + rowB];
    const int prA = warp*16 + fr;       // local P row

    float o[16][4];
    #pragma unroll
    for (int i = 0; i < 16; i++)
        #pragma unroll
        for (int j = 0; j < 4; j++) o[i][j] = 0.f;
    float mA = -INFINITY, mB = -INFINITY, lA = 0.f, lB = 0.f;

    for (int kt = 0; kt <= qb; kt++) {
        __syncthreads();   // prev tile done with Ks/Vs

        #pragma unroll
        for (int j = 0; j < 8; j++) {
            const int ch = lch0 + j;
            const uint32_t doff = lrow*256 + (((uint32_t)ch ^ lsw) << 4);
            cp_async16(ksb + doff, Kg + (size_t)(kt*64 + lrow)*Cc + ch*8);
            cp_async16(vsb + doff, Vg + (size_t)(kt*64 + lrow)*Cc + ch*8);
        }
        cp_commit(); cp_wait0();
        __syncthreads();

        // ---- S = Q K^T ----
        float sa[8][4];
        #pragma unroll
        for (int ni = 0; ni < 8; ni++)
            #pragma unroll
            for (int j = 0; j < 4; j++) sa[ni][j] = 0.f;

        #pragma unroll
        for (int kb = 0; kb < 8; kb++) {
            uint32_t bq[4][4];
            #pragma unroll
            for (int pi = 0; pi < 4; pi++) {
                const int n = pi*16 + b_nsel*8 + (lane & 7);
                ldsm_x4(bq[pi], ksb + n*256 + (((uint32_t)(2*kb + b_ksel) ^ (uint32_t)(n & 7)) << 4));
            }
            #pragma unroll
            for (int ni = 0; ni < 8; ni++)
                mma_f16(sa[ni], qf[kb], &bq[ni >> 1][(ni & 1) * 2]);
        }

        // ---- mask + online softmax ----
        float mxA = -INFINITY, mxB = -INFINITY;
        #pragma unroll
        for (int ni = 0; ni < 8; ni++) {
            const int c0 = kt*64 + ni*8 + 2*fc;
            float s0 = sa[ni][0]*scale, s1 = sa[ni][1]*scale;
            float s2 = sa[ni][2]*scale, s3 = sa[ni][3]*scale;
            if (pmA == 0) { s0 = -1e9f; s1 = -1e9f; }
            if (pmB == 0) { s2 = -1e9f; s3 = -1e9f; }
            if (kt == qb) {
                if (c0     > rowA) s0 = -INFINITY;
                if (c0 + 1 > rowA) s1 = -INFINITY;
                if (c0     > rowB) s2 = -INFINITY;
                if (c0 + 1 > rowB) s3 = -INFINITY;
            }
            sa[ni][0] = s0; sa[ni][1] = s1; sa[ni][2] = s2; sa[ni][3] = s3;
            mxA = fmaxf(mxA, fmaxf(s0, s1));
            mxB = fmaxf(mxB, fmaxf(s2, s3));
        }
        mxA = fmaxf(mxA, __shfl_xor_sync(0xffffffffu, mxA, 1));
        mxA = fmaxf(mxA, __shfl_xor_sync(0xffffffffu, mxA, 2));
        mxB = fmaxf(mxB, __shfl_xor_sync(0xffffffffu, mxB, 1));
        mxB = fmaxf(mxB, __shfl_xor_sync(0xffffffffu, mxB, 2));

        const float mnA = fmaxf(mA, mxA), mnB = fmaxf(mB, mxB);
        const float sfA = __expf(mA - mnA), sfB = __expf(mB - mnB);
        mA = mnA; mB = mnB;

        float suA = 0.f, suB = 0.f;
        #pragma unroll
        for (int ni = 0; ni < 8; ni++) {
            __half2 h01 = __floats2half2_rn(__expf(sa[ni][0] - mA), __expf(sa[ni][1] - mA));
            __half2 h23 = __floats2half2_rn(__expf(sa[ni][2] - mB), __expf(sa[ni][3] - mB));
            const float2 f01 = __half22float2(h01);
            const float2 f23 = __half22float2(h23);
            suA += f01.x + f01.y; suB += f23.x + f23.y;
            // P[row][col], row 128B, chunk = ni, intra halves = 2*fc
            const uint32_t aoA = psb + prA*128     + (((uint32_t)ni ^ (uint32_t)(prA & 7))       << 4) + fc*4;
            const uint32_t aoB = psb + (prA+8)*128 + (((uint32_t)ni ^ (uint32_t)((prA+8) & 7))   << 4) + fc*4;
            *(__half2*)(smc + (aoA - sb)) = h01;
            *(__half2*)(smc + (aoB - sb)) = h23;
        }
        suA += __shfl_xor_sync(0xffffffffu, suA, 1);
        suA += __shfl_xor_sync(0xffffffffu, suA, 2);
        suB += __shfl_xor_sync(0xffffffffu, suB, 1);
        suB += __shfl_xor_sync(0xffffffffu, suB, 2);
        lA = lA*sfA + suA;
        lB = lB*sfB + suB;
        #pragma unroll
        for (int ni = 0; ni < 16; ni++) {
            o[ni][0] *= sfA; o[ni][1] *= sfA;
            o[ni][2] *= sfB; o[ni][3] *= sfB;
        }
        __syncwarp();   // P rows are per-warp private: warp sync suffices

        // ---- O += P V (P frags A-style, V frags via ldmatrix.trans) ----
        #pragma unroll
        for (int kb = 0; kb < 4; kb++) {
            uint32_t pa[4];
            ldsm_x4(pa, psb + a_row*128 + (((uint32_t)(2*kb + a_ksel) ^ (uint32_t)(a_row & 7)) << 4));
            #pragma unroll
            for (int di = 0; di < 8; di++) {
                uint32_t bv[4];
                const int sv = kb*16 + v_ssel*8 + (lane & 7);
                const uint32_t ch = (uint32_t)(2*di + v_dsel);
                ldsm_x4_t(bv, vsb + sv*256 + ((ch ^ (uint32_t)(sv & 7)) << 4));
                mma_f16(o[di*2    ], pa, &bv[0]);
                mma_f16(o[di*2 + 1], pa, &bv[2]);
            }
        }
    }

    // ---- epilogue: ctx = O / l, fp16 for the output projection ----
    const float iA = 1.f / lA, iB = 1.f / lB;
    __half* cpA = g_ctxh + (size_t)(b*Tt + rowA)*Cc + hoff;
    __half* cpB = g_ctxh + (size_t)(b*Tt + rowB)*Cc + hoff;
    #pragma unroll
    for (int ni = 0; ni < 16; ni++) {
        const int d0 = ni*8 + 2*fc;
        *(__half2*)(cpA + d0) = __floats2half2_rn(o[ni][0]*iA, o[ni][1]*iA);
        *(__half2*)(cpB + d0) = __floats2half2_rn(o[ni][2]*iB, o[ni][3]*iB);
    }
}

// ===========================================================================
extern "C" void kernel_launch(void* const* d_in, const int* in_sizes, int n_in,
                              void* d_out, int out_size)
{
    (void)in_sizes; (void)n_in; (void)out_size;
    const float* x  = (const float*)d_in[0];
    const int*   pm = (const int*)  d_in[1];
    const float* Wq = (const float*)d_in[2];
    const float* Wk = (const float*)d_in[3];
    const float* Wv = (const float*)d_in[4];
    const float* Wp = (const float*)d_in[5];
    const float* bp = (const float*)d_in[6];
    float* out = (float*)d_out;

    __half *xh, *wqh, *wkh, *wvh, *wph, *qh, *kh, *vh, *ctxh;
    cudaGetSymbolAddress((void**)&xh,   g_xh);
    cudaGetSymbolAddress((void**)&wqh,  g_wqh);
    cudaGetSymbolAddress((void**)&wkh,  g_wkh);
    cudaGetSymbolAddress((void**)&wvh,  g_wvh);
    cudaGetSymbolAddress((void**)&wph,  g_wph);
    cudaGetSymbolAddress((void**)&qh,   g_qh);
    cudaGetSymbolAddress((void**)&kh,   g_kh);
    cudaGetSymbolAddress((void**)&vh,   g_vh);
    cudaGetSymbolAddress((void**)&ctxh, g_ctxh);

    const int nb = (NTOK*Cc/4 + 255) / 256;
    tohalf_all<<<dim3(nb, 1, 5), 256>>>(
        (const float4*)x,  xh,
        (const float4*)Wq, wqh,
        (const float4*)Wk, wkh,
        (const float4*)Wv, wvh,
        (const float4*)Wp, wph);

    cudaFuncSetAttribute(gemm_qkv, cudaFuncAttributeMaxDynamicSharedMemorySize, G_SMEM);
    cudaFuncSetAttribute(gemm_out, cudaFuncAttributeMaxDynamicSharedMemorySize, G_SMEM);
    cudaFuncSetAttribute(attn_f16, cudaFuncAttributeMaxDynamicSharedMemorySize, AT_SMEM);

    gemm_qkv<<<dim3(Cc/256, NTOK/128, 3), 256, G_SMEM>>>(xh, wqh, wkh, wvh, qh, kh, vh);
    attn_f16<<<dim3(Tt/64, Hh, Bb), 128, AT_SMEM>>>(pm);
    gemm_out<<<dim3(Cc/256, NTOK/128), 256, G_SMEM>>>(ctxh, wph, bp, out);
}

// round 9
// speedup vs baseline: 2.0811x; 1.0350x over previous
#include <cuda_runtime.h>
#include <cuda_fp16.h>
#include <cstdint>
#include <math.h>

#define Bb 2
#define Tt 2048
#define Cc 2048
#define Hh 16
#define Dd 128
#define NTOK (Bb*Tt)   // 4096

// Scratch (device globals: no runtime allocation allowed)
__device__ __half g_xh [(size_t)NTOK*Cc];
__device__ __half g_wqh[(size_t)Cc*Cc];
__device__ __half g_wkh[(size_t)Cc*Cc];
__device__ __half g_wvh[(size_t)Cc*Cc];
__device__ __half g_wph[(size_t)Cc*Cc];
__device__ __half g_qh [(size_t)NTOK*Cc];
__device__ __half g_kh [(size_t)NTOK*Cc];
__device__ __half g_vh [(size_t)NTOK*Cc];
__device__ __half g_ctxh[(size_t)NTOK*Cc];

// ===========================================================================
// helpers
// ===========================================================================
__device__ __forceinline__ uint32_t smem_u32(const void* p) {
    uint32_t a;
    asm("{ .reg .u64 t; cvta.to.shared.u64 t, %1; cvt.u32.u64 %0, t; }" : "=r"(a) : "l"(p));
    return a;
}
__device__ __forceinline__ void cp_async16(uint32_t dst, const void* src) {
    asm volatile("cp.async.cg.shared.global [%0], [%1], 16;" :: "r"(dst), "l"(src) : "memory");
}
__device__ __forceinline__ void cp_commit() {
    asm volatile("cp.async.commit_group;" ::: "memory");
}
__device__ __forceinline__ void cp_wait1() {
    asm volatile("cp.async.wait_group 1;" ::: "memory");
}
__device__ __forceinline__ void cp_wait0() {
    asm volatile("cp.async.wait_group 0;" ::: "memory");
}
__device__ __forceinline__ void ldsm_x4(uint32_t* r, uint32_t addr) {
    asm volatile("ldmatrix.sync.aligned.m8n8.x4.shared.b16 {%0,%1,%2,%3}, [%4];"
                 : "=r"(r[0]), "=r"(r[1]), "=r"(r[2]), "=r"(r[3]) : "r"(addr));
}
__device__ __forceinline__ void ldsm_x4_t(uint32_t* r, uint32_t addr) {
    asm volatile("ldmatrix.sync.aligned.m8n8.x4.trans.shared.b16 {%0,%1,%2,%3}, [%4];"
                 : "=r"(r[0]), "=r"(r[1]), "=r"(r[2]), "=r"(r[3]) : "r"(addr));
}
// m16n8k16 fp16 MMA, fp32 accumulate
__device__ __forceinline__ void mma_f16(float* c, const uint32_t* a, const uint32_t* b) {
    asm volatile(
        "mma.sync.aligned.m16n8k16.row.col.f32.f16.f16.f32 "
        "{%0,%1,%2,%3}, {%4,%5,%6,%7}, {%8,%9}, {%0,%1,%2,%3};"
        : "+f"(c[0]), "+f"(c[1]), "+f"(c[2]), "+f"(c[3])
        : "r"(a[0]), "r"(a[1]), "r"(a[2]), "r"(a[3]), "r"(b[0]), "r"(b[1]));
}

// ===========================================================================
// fp32 -> fp16 conversion (z selects buffer)
// ===========================================================================
__global__ void __launch_bounds__(256) tohalf_all(
    const float4* __restrict__ x,  __half* __restrict__ xr,
    const float4* __restrict__ w0, __half* __restrict__ r0,
    const float4* __restrict__ w1, __half* __restrict__ r1,
    const float4* __restrict__ w2, __half* __restrict__ r2,
    const float4* __restrict__ w3, __half* __restrict__ r3)
{
    const int z = blockIdx.z;
    const float4* src; __half* dst; int n4;
    if      (z == 0) { src = x;  dst = xr; n4 = NTOK*Cc/4; }
    else if (z == 1) { src = w0; dst = r0; n4 = Cc*Cc/4; }
    else if (z == 2) { src = w1; dst = r1; n4 = Cc*Cc/4; }
    else if (z == 3) { src = w2; dst = r2; n4 = Cc*Cc/4; }
    else             { src = w3; dst = r3; n4 = Cc*Cc/4; }
    int i = blockIdx.x * blockDim.x + threadIdx.x;
    if (i < n4) {
        float4 v = src[i];
        *(__half2*)(dst + (size_t)i*4)     = __floats2half2_rn(v.x, v.y);
        *(__half2*)(dst + (size_t)i*4 + 2) = __floats2half2_rn(v.z, v.w);
    }
}

// ===========================================================================
// fp16 mma.sync GEMM: C[m,n] = sum_k A[m,k]*W[n,k] (+ bias[n])
// CTA 128x256, 8 warps, warp tile 64x64, BK=64 halves, 3 stages.
// ===========================================================================
#define G_BK     64
#define G_ABY    (128*128)
#define G_BBY    (256*128)
#define G_STAGES 3
#define G_SMEM   (G_STAGES*(G_ABY+G_BBY))      // 147456
#define G_NSTEP  (Cc / G_BK)                   // 32

template<bool HALF_OUT>
__device__ __forceinline__ void gemm_body(const __half* __restrict__ A,
                                          const __half* __restrict__ W,
                                          const float* __restrict__ bias,
                                          float* __restrict__ Cf,
                                          __half* __restrict__ Ch)
{
    extern __shared__ char smc[];
    const uint32_t asb = smem_u32(smc);
    const uint32_t bsb = asb + G_STAGES * G_ABY;

    const int tid  = threadIdx.x;
    const int lane = tid & 31;
    const int warp = tid >> 5;
    const int n0 = blockIdx.x * 256;
    const int m0 = blockIdx.y * 128;
    const int wm = (warp & 1) * 64;
    const int wn = (warp >> 1) * 64;
    const int fr = lane >> 2;
    const int fc = lane & 3;

    const int a_msel = (lane >> 3) & 1;
    const int a_ksel = lane >> 4;
    const int b_nsel = (lane >> 4) & 1;
    const int b_ksel = (lane >> 3) & 1;
    uint32_t a_off[4], a_sw[4], b_off[4], b_sw[4];
    #pragma unroll
    for (int mi = 0; mi < 4; mi++) {
        const int r = wm + mi*16 + a_msel*8 + (lane & 7);
        a_off[mi] = (uint32_t)r * 128;
        a_sw[mi]  = (uint32_t)(r & 7);
    }
    #pragma unroll
    for (int pi = 0; pi < 4; pi++) {
        const int n = wn + pi*16 + b_nsel*8 + (lane & 7);
        b_off[pi] = (uint32_t)n * 128;
        b_sw[pi]  = (uint32_t)(n & 7);
    }

    const int lrA = tid >> 1;
    const int ljA = (tid & 1) * 4;
    const __half* Ag = A + (size_t)(m0 + lrA) * Cc;
    const __half* Wg = W + (size_t)(n0 + tid) * Cc;
    const uint32_t swA = (uint32_t)(lrA & 7);
    const uint32_t swB = (uint32_t)(tid & 7);

    float acc[4][8][4];
    #pragma unroll
    for (int i = 0; i < 4; i++)
        #pragma unroll
        for (int j = 0; j < 8; j++)
            #pragma unroll
            for (int q = 0; q < 4; q++) acc[i][j][q] = 0.f;

    #define G_LOAD(s, st) do {                                                  \
        const uint32_t sa = asb + (st) * G_ABY;                                  \
        const uint32_t sb = bsb + (st) * G_BBY;                                  \
        const int kof = (s) * G_BK;                                              \
        _Pragma("unroll")                                                        \
        for (int j = 0; j < 4; j++) {                                            \
            const int ch = ljA + j;                                              \
            cp_async16(sa + lrA*128 + (((uint32_t)ch ^ swA) << 4),               \
                       Ag + kof + ch*8);                                         \
        }                                                                        \
        _Pragma("unroll")                                                        \
        for (int j = 0; j < 8; j++) {                                            \
            cp_async16(sb + tid*128 + (((uint32_t)j ^ swB) << 4),                \
                       Wg + kof + j*8);                                          \
        }                                                                        \
    } while (0)

    #define G_FRAG(buf, Ab, Bb_, ks) do {                                        \
        const uint32_t ka  = (uint32_t)(2*(ks) + a_ksel);                        \
        const uint32_t kb_ = (uint32_t)(2*(ks) + b_ksel);                        \
        _Pragma("unroll")                                                        \
        for (int mi = 0; mi < 4; mi++)                                           \
            ldsm_x4(af[buf][mi], (Ab) + a_off[mi] + ((ka ^ a_sw[mi]) << 4));     \
        _Pragma("unroll")                                                        \
        for (int pi = 0; pi < 4; pi++)                                           \
            ldsm_x4(bfr[buf][pi], (Bb_) + b_off[pi] + ((kb_ ^ b_sw[pi]) << 4));  \
    } while (0)

    G_LOAD(0, 0); cp_commit();
    G_LOAD(1, 1); cp_commit();

    uint32_t af[2][4][4], bfr[2][4][4];

    for (int s = 0; s < G_NSTEP; s++) {
        cp_wait1();
        __syncthreads();
        if (s + 2 < G_NSTEP) { G_LOAD(s + 2, (s + 2) % G_STAGES); }
        cp_commit();

        const uint32_t A_sa = asb + (s % G_STAGES) * G_ABY;
        const uint32_t B_sa = bsb + (s % G_STAGES) * G_BBY;

        G_FRAG(0, A_sa, B_sa, 0);
        #pragma unroll
        for (int ks = 0; ks < 4; ks++) {
            const int cur = ks & 1;
            if (ks < 3) G_FRAG(cur ^ 1, A_sa, B_sa, ks + 1);
            #pragma unroll
            for (int mi = 0; mi < 4; mi++)
                #pragma unroll
                for (int ni = 0; ni < 8; ni++)
                    mma_f16(acc[mi][ni], af[cur][mi], &bfr[cur][ni >> 1][(ni & 1) * 2]);
        }
    }
    #undef G_LOAD
    #undef G_FRAG
    __syncthreads();

    #pragma unroll
    for (int mi = 0; mi < 4; mi++) {
        const int r0 = m0 + wm + mi*16 + fr;
        #pragma unroll
        for (int ni = 0; ni < 8; ni++) {
            const int col = n0 + wn + ni*8 + fc*2;
            if (HALF_OUT) {
                *(__half2*)(Ch + (size_t)r0       * Cc + col) =
                    __floats2half2_rn(acc[mi][ni][0], acc[mi][ni][1]);
                *(__half2*)(Ch + (size_t)(r0 + 8) * Cc + col) =
                    __floats2half2_rn(acc[mi][ni][2], acc[mi][ni][3]);
            } else {
                const float b0 = __ldg(bias + col), b1 = __ldg(bias + col + 1);
                *(float2*)(Cf + (size_t)r0       * Cc + col) =
                    make_float2(acc[mi][ni][0] + b0, acc[mi][ni][1] + b1);
                *(float2*)(Cf + (size_t)(r0 + 8) * Cc + col) =
                    make_float2(acc[mi][ni][2] + b0, acc[mi][ni][3] + b1);
            }
        }
    }
}

__global__ void __launch_bounds__(256, 1)
gemm_out(const __half* __restrict__ A, const __half* __restrict__ W,
         const float* __restrict__ bias, float* __restrict__ C) {
    gemm_body<false>(A, W, bias, C, nullptr);
}

__global__ void __launch_bounds__(256, 1)
gemm_qkv(const __half* __restrict__ A,
         const __half* __restrict__ W0, const __half* __restrict__ W1,
         const __half* __restrict__ W2,
         __half* __restrict__ C0, __half* __restrict__ C1, __half* __restrict__ C2) {
    const __half* W = (blockIdx.z == 0) ? W0 : (blockIdx.z == 1) ? W1 : W2;
    __half*       C = (blockIdx.z == 0) ? C0 : (blockIdx.z == 1) ? C1 : C2;
    gemm_body<true>(A, W, nullptr, nullptr, C);
}

// ===========================================================================
// Flash-attention, fp16 mma.sync, double-buffered K/V (2-stage cp.async).
// CTA = 128 threads, one (b,h,64-query tile). smem 88KB -> 2 CTAs/SM.
// Tiles launched descending-qb for causal load balance.
// ===========================================================================
#define AT_Q  0
#define AT_K0 16384
#define AT_V0 49152
#define AT_P  81920
#define AT_SMEM 90112   // 16 + 2x16 + 2x16 + 8 KB

__global__ void __launch_bounds__(128, 2) attn_f16(const int* __restrict__ pm)
{
    extern __shared__ char smc[];
    const uint32_t sb  = smem_u32(smc);
    const uint32_t qsb = sb + AT_Q;
    const uint32_t psb = sb + AT_P;

    const int qb = (gridDim.x - 1) - blockIdx.x;   // descending order
    const int h  = blockIdx.y;
    const int b  = blockIdx.z;
    const int tid  = threadIdx.x;
    const int lane = tid & 31;
    const int warp = tid >> 5;
    const int fr = lane >> 2;
    const int fc = lane & 3;

    const int a_msel = (lane >> 3) & 1;
    const int a_ksel = lane >> 4;
    const int b_nsel = (lane >> 4) & 1;
    const int b_ksel = (lane >> 3) & 1;
    const int v_ssel = (lane >> 3) & 1;
    const int v_dsel = (lane >> 4) & 1;
    const int a_row  = warp*16 + a_msel*8 + (lane & 7);

    const size_t hoff = (size_t)h * Dd;
    const __half* Qg = g_qh + (size_t)b * Tt * Cc + hoff;
    const __half* Kg = g_kh + (size_t)b * Tt * Cc + hoff;
    const __half* Vg = g_vh + (size_t)b * Tt * Cc + hoff;
    const int q0 = qb * 64;

    // loader indices: 64 rows x 16 chunks, 2 threads/row, 8 chunks each
    const int lrow = tid >> 1;
    const int lch0 = (tid & 1) * 8;
    const uint32_t lsw = (uint32_t)(lrow & 7);

    #define AT_LOADKV(kt, st) do {                                                 \
        const uint32_t kb_ = sb + AT_K0 + (st)*16384;                              \
        const uint32_t vb_ = sb + AT_V0 + (st)*16384;                              \
        _Pragma("unroll")                                                          \
        for (int j = 0; j < 8; j++) {                                              \
            const int ch = lch0 + j;                                               \
            const uint32_t doff = lrow*256 + (((uint32_t)ch ^ lsw) << 4);          \
            cp_async16(kb_ + doff, Kg + (size_t)((kt)*64 + lrow)*Cc + ch*8);       \
            cp_async16(vb_ + doff, Vg + (size_t)((kt)*64 + lrow)*Cc + ch*8);       \
        }                                                                          \
        cp_commit();                                                               \
    } while (0)

    // ---- load Q tile + prologue K/V(0) ----
    #pragma unroll
    for (int j = 0; j < 8; j++) {
        const int ch = lch0 + j;
        cp_async16(qsb + lrow*256 + (((uint32_t)ch ^ lsw) << 4),
                   Qg + (size_t)(q0 + lrow)*Cc + ch*8);
    }
    cp_commit();
    AT_LOADKV(0, 0);
    cp_wait1();          // Q group done (K/V(0) may still be in flight)
    __syncthreads();

    // ---- Q fragments, register-resident ----
    uint32_t qf[8][4];
    #pragma unroll
    for (int kb = 0; kb < 8; kb++)
        ldsm_x4(qf[kb], qsb + a_row*256 + (((uint32_t)(2*kb + a_ksel) ^ (uint32_t)(a_row & 7)) << 4));

    const float scale = 0.08838834764831845f;
    const int rowA = q0 + warp*16 + fr;
    const int rowB = rowA + 8;
    const int pmA = pm[b*Tt + rowA];
    const int pmB = pm[b*Tt + rowB];
    const int prA = warp*16 + fr;

    float o[16][4];
    #pragma unroll
    for (int i = 0; i < 16; i++)
        #pragma unroll
        for (int j = 0; j < 4; j++) o[i][j] = 0.f;
    float mA = -INFINITY, mB = -INFINITY, lA = 0.f, lB = 0.f;

    for (int kt = 0; kt <= qb; kt++) {
        const int cur = kt & 1;
        const bool more = (kt + 1 <= qb);
        if (more) AT_LOADKV(kt + 1, cur ^ 1);   // prefetch next tile (other stage)
        if (more) cp_wait1(); else cp_wait0();  // current stage resident
        __syncthreads();

        const uint32_t ksb = sb + AT_K0 + cur*16384;
        const uint32_t vsb = sb + AT_V0 + cur*16384;

        // ---- S = Q K^T ----
        float sa[8][4];
        #pragma unroll
        for (int ni = 0; ni < 8; ni++)
            #pragma unroll
            for (int j = 0; j < 4; j++) sa[ni][j] = 0.f;

        #pragma unroll
        for (int kb = 0; kb < 8; kb++) {
            uint32_t bq[4][4];
            #pragma unroll
            for (int pi = 0; pi < 4; pi++) {
                const int n = pi*16 + b_nsel*8 + (lane & 7);
                ldsm_x4(bq[pi], ksb + n*256 + (((uint32_t)(2*kb + b_ksel) ^ (uint32_t)(n & 7)) << 4));
            }
            #pragma unroll
            for (int ni = 0; ni < 8; ni++)
                mma_f16(sa[ni], qf[kb], &bq[ni >> 1][(ni & 1) * 2]);
        }

        // ---- mask + online softmax ----
        float mxA = -INFINITY, mxB = -INFINITY;
        #pragma unroll
        for (int ni = 0; ni < 8; ni++) {
            const int c0 = kt*64 + ni*8 + 2*fc;
            float s0 = sa[ni][0]*scale, s1 = sa[ni][1]*scale;
            float s2 = sa[ni][2]*scale, s3 = sa[ni][3]*scale;
            if (pmA == 0) { s0 = -1e9f; s1 = -1e9f; }
            if (pmB == 0) { s2 = -1e9f; s3 = -1e9f; }
            if (kt == qb) {
                if (c0     > rowA) s0 = -INFINITY;
                if (c0 + 1 > rowA) s1 = -INFINITY;
                if (c0     > rowB) s2 = -INFINITY;
                if (c0 + 1 > rowB) s3 = -INFINITY;
            }
            sa[ni][0] = s0; sa[ni][1] = s1; sa[ni][2] = s2; sa[ni][3] = s3;
            mxA = fmaxf(mxA, fmaxf(s0, s1));
            mxB = fmaxf(mxB, fmaxf(s2, s3));
        }
        mxA = fmaxf(mxA, __shfl_xor_sync(0xffffffffu, mxA, 1));
        mxA = fmaxf(mxA, __shfl_xor_sync(0xffffffffu, mxA, 2));
        mxB = fmaxf(mxB, __shfl_xor_sync(0xffffffffu, mxB, 1));
        mxB = fmaxf(mxB, __shfl_xor_sync(0xffffffffu, mxB, 2));

        const float mnA = fmaxf(mA, mxA), mnB = fmaxf(mB, mxB);
        const float sfA = __expf(mA - mnA), sfB = __expf(mB - mnB);
        mA = mnA; mB = mnB;

        float suA = 0.f, suB = 0.f;
        #pragma unroll
        for (int ni = 0; ni < 8; ni++) {
            __half2 h01 = __floats2half2_rn(__expf(sa[ni][0] - mA), __expf(sa[ni][1] - mA));
            __half2 h23 = __floats2half2_rn(__expf(sa[ni][2] - mB), __expf(sa[ni][3] - mB));
            const float2 f01 = __half22float2(h01);
            const float2 f23 = __half22float2(h23);
            suA += f01.x + f01.y; suB += f23.x + f23.y;
            const uint32_t aoA = psb + prA*128     + (((uint32_t)ni ^ (uint32_t)(prA & 7))     << 4) + fc*4;
            const uint32_t aoB = psb + (prA+8)*128 + (((uint32_t)ni ^ (uint32_t)((prA+8) & 7)) << 4) + fc*4;
            *(__half2*)(smc + (aoA - sb)) = h01;
            *(__half2*)(smc + (aoB - sb)) = h23;
        }
        suA += __shfl_xor_sync(0xffffffffu, suA, 1);
        suA += __shfl_xor_sync(0xffffffffu, suA, 2);
        suB += __shfl_xor_sync(0xffffffffu, suB, 1);
        suB += __shfl_xor_sync(0xffffffffu, suB, 2);
        lA = lA*sfA + suA;
        lB = lB*sfB + suB;
        #pragma unroll
        for (int ni = 0; ni < 16; ni++) {
            o[ni][0] *= sfA; o[ni][1] *= sfA;
            o[ni][2] *= sfB; o[ni][3] *= sfB;
        }
        __syncwarp();   // P rows are per-warp private

        // ---- O += P V ----
        #pragma unroll
        for (int kb = 0; kb < 4; kb++) {
            uint32_t pa[4];
            ldsm_x4(pa, psb + a_row*128 + (((uint32_t)(2*kb + a_ksel) ^ (uint32_t)(a_row & 7)) << 4));
            #pragma unroll
            for (int di = 0; di < 8; di++) {
                uint32_t bv[4];
                const int sv = kb*16 + v_ssel*8 + (lane & 7);
                const uint32_t ch = (uint32_t)(2*di + v_dsel);
                ldsm_x4_t(bv, vsb + sv*256 + ((ch ^ (uint32_t)(sv & 7)) << 4));
                mma_f16(o[di*2    ], pa, &bv[0]);
                mma_f16(o[di*2 + 1], pa, &bv[2]);
            }
        }
        __syncthreads();   // all warps done with stage `cur` before it is overwritten
    }
    #undef AT_LOADKV

    // ---- epilogue: ctx = O / l, fp16 for the output projection ----
    const float iA = 1.f / lA, iB = 1.f / lB;
    __half* cpA = g_ctxh + (size_t)(b*Tt + rowA)*Cc + hoff;
    __half* cpB = g_ctxh + (size_t)(b*Tt + rowB)*Cc + hoff;
    #pragma unroll
    for (int ni = 0; ni < 16; ni++) {
        const int d0 = ni*8 + 2*fc;
        *(__half2*)(cpA + d0) = __floats2half2_rn(o[ni][0]*iA, o[ni][1]*iA);
        *(__half2*)(cpB + d0) = __floats2half2_rn(o[ni][2]*iB, o[ni][3]*iB);
    }
}

// ===========================================================================
extern "C" void kernel_launch(void* const* d_in, const int* in_sizes, int n_in,
                              void* d_out, int out_size)
{
    (void)in_sizes; (void)n_in; (void)out_size;
    const float* x  = (const float*)d_in[0];
    const int*   pm = (const int*)  d_in[1];
    const float* Wq = (const float*)d_in[2];
    const float* Wk = (const float*)d_in[3];
    const float* Wv = (const float*)d_in[4];
    const float* Wp = (const float*)d_in[5];
    const float* bp = (const float*)d_in[6];
    float* out = (float*)d_out;

    __half *xh, *wqh, *wkh, *wvh, *wph, *qh, *kh, *vh, *ctxh;
    cudaGetSymbolAddress((void**)&xh,   g_xh);
    cudaGetSymbolAddress((void**)&wqh,  g_wqh);
    cudaGetSymbolAddress((void**)&wkh,  g_wkh);
    cudaGetSymbolAddress((void**)&wvh,  g_wvh);
    cudaGetSymbolAddress((void**)&wph,  g_wph);
    cudaGetSymbolAddress((void**)&qh,   g_qh);
    cudaGetSymbolAddress((void**)&kh,   g_kh);
    cudaGetSymbolAddress((void**)&vh,   g_vh);
    cudaGetSymbolAddress((void**)&ctxh, g_ctxh);

    const int nb = (NTOK*Cc/4 + 255) / 256;
    tohalf_all<<<dim3(nb, 1, 5), 256>>>(
        (const float4*)x,  xh,
        (const float4*)Wq, wqh,
        (const float4*)Wk, wkh,
        (const float4*)Wv, wvh,
        (const float4*)Wp, wph);

    cudaFuncSetAttribute(gemm_qkv, cudaFuncAttributeMaxDynamicSharedMemorySize, G_SMEM);
    cudaFuncSetAttribute(gemm_out, cudaFuncAttributeMaxDynamicSharedMemorySize, G_SMEM);
    cudaFuncSetAttribute(attn_f16, cudaFuncAttributeMaxDynamicSharedMemorySize, AT_SMEM);

    gemm_qkv<<<dim3(Cc/256, NTOK/128, 3), 256, G_SMEM>>>(xh, wqh, wkh, wvh, qh, kh, vh);
    attn_f16<<<dim3(Tt/64, Hh, Bb), 128, AT_SMEM>>>(pm);
    gemm_out<<<dim3(Cc/256, NTOK/128), 256, G_SMEM>>>(ctxh, wph, bp, out);
}

// round 10
// speedup vs baseline: 2.4843x; 1.1937x over previous
#include <cuda_runtime.h>
#include <cuda_fp16.h>
#include <cstdint>
#include <math.h>

#define Bb 2
#define Tt 2048
#define Cc 2048
#define Hh 16
#define Dd 128
#define NTOK (Bb*Tt)   // 4096

// Scratch (device globals: no runtime allocation allowed)
__device__ __half g_xh [(size_t)NTOK*Cc];
__device__ __half g_wqh[(size_t)Cc*Cc];
__device__ __half g_wkh[(size_t)Cc*Cc];
__device__ __half g_wvh[(size_t)Cc*Cc];
__device__ __half g_wph[(size_t)Cc*Cc];
__device__ __half g_qh [(size_t)NTOK*Cc];
__device__ __half g_kh [(size_t)NTOK*Cc];
__device__ __half g_vh [(size_t)NTOK*Cc];
__device__ __half g_ctxh[(size_t)NTOK*Cc];

// ===========================================================================
// helpers
// ===========================================================================
__device__ __forceinline__ uint32_t smem_u32(const void* p) {
    uint32_t a;
    asm("{ .reg .u64 t; cvta.to.shared.u64 t, %1; cvt.u32.u64 %0, t; }" : "=r"(a) : "l"(p));
    return a;
}
__device__ __forceinline__ void cp_async16(uint32_t dst, const void* src) {
    asm volatile("cp.async.cg.shared.global [%0], [%1], 16;" :: "r"(dst), "l"(src) : "memory");
}
__device__ __forceinline__ void cp_commit() {
    asm volatile("cp.async.commit_group;" ::: "memory");
}
__device__ __forceinline__ void cp_wait1() {
    asm volatile("cp.async.wait_group 1;" ::: "memory");
}
__device__ __forceinline__ void cp_wait0() {
    asm volatile("cp.async.wait_group 0;" ::: "memory");
}
__device__ __forceinline__ void ldsm_x4(uint32_t* r, uint32_t addr) {
    asm volatile("ldmatrix.sync.aligned.m8n8.x4.shared.b16 {%0,%1,%2,%3}, [%4];"
                 : "=r"(r[0]), "=r"(r[1]), "=r"(r[2]), "=r"(r[3]) : "r"(addr));
}
__device__ __forceinline__ void ldsm_x4_t(uint32_t* r, uint32_t addr) {
    asm volatile("ldmatrix.sync.aligned.m8n8.x4.trans.shared.b16 {%0,%1,%2,%3}, [%4];"
                 : "=r"(r[0]), "=r"(r[1]), "=r"(r[2]), "=r"(r[3]) : "r"(addr));
}
// m16n8k16 fp16 MMA, fp32 accumulate
__device__ __forceinline__ void mma_f16(float* c, const uint32_t* a, const uint32_t* b) {
    asm volatile(
        "mma.sync.aligned.m16n8k16.row.col.f32.f16.f16.f32 "
        "{%0,%1,%2,%3}, {%4,%5,%6,%7}, {%8,%9}, {%0,%1,%2,%3};"
        : "+f"(c[0]), "+f"(c[1]), "+f"(c[2]), "+f"(c[3])
        : "r"(a[0]), "r"(a[1]), "r"(a[2]), "r"(a[3]), "r"(b[0]), "r"(b[1]));
}

// ===========================================================================
// fp32 -> fp16 conversion (z selects buffer)
// ===========================================================================
__global__ void __launch_bounds__(256) tohalf_all(
    const float4* __restrict__ x,  __half* __restrict__ xr,
    const float4* __restrict__ w0, __half* __restrict__ r0,
    const float4* __restrict__ w1, __half* __restrict__ r1,
    const float4* __restrict__ w2, __half* __restrict__ r2,
    const float4* __restrict__ w3, __half* __restrict__ r3)
{
    const int z = blockIdx.z;
    const float4* src; __half* dst; int n4;
    if      (z == 0) { src = x;  dst = xr; n4 = NTOK*Cc/4; }
    else if (z == 1) { src = w0; dst = r0; n4 = Cc*Cc/4; }
    else if (z == 2) { src = w1; dst = r1; n4 = Cc*Cc/4; }
    else if (z == 3) { src = w2; dst = r2; n4 = Cc*Cc/4; }
    else             { src = w3; dst = r3; n4 = Cc*Cc/4; }
    int i = blockIdx.x * blockDim.x + threadIdx.x;
    if (i < n4) {
        float4 v = src[i];
        *(__half2*)(dst + (size_t)i*4)     = __floats2half2_rn(v.x, v.y);
        *(__half2*)(dst + (size_t)i*4 + 2) = __floats2half2_rn(v.z, v.w);
    }
}

// ===========================================================================
// fp16 mma.sync GEMM: C[m,n] = sum_k A[m,k]*W[n,k] (+ bias[n])
// CTA 128x128, 256 threads (8 warps, warp tile 64x32), BK=64, 3 stages,
// 96KB smem -> 2 CTAs/SM (16 warps/SM). Single-buffered frags (reg cap 128).
// ===========================================================================
#define G_BK     64
#define G_TBY    (128*128)                     // 16KB per tile per stage
#define G_STAGES 3
#define G_SMEM   (G_STAGES*2*G_TBY)            // 98304
#define G_NSTEP  (Cc / G_BK)                   // 32

template<bool HALF_OUT>
__device__ __forceinline__ void gemm_body(const __half* __restrict__ A,
                                          const __half* __restrict__ W,
                                          const float* __restrict__ bias,
                                          float* __restrict__ Cf,
                                          __half* __restrict__ Ch)
{
    extern __shared__ char smc[];
    const uint32_t asb = smem_u32(smc);
    const uint32_t bsb = asb + G_STAGES * G_TBY;

    const int tid  = threadIdx.x;
    const int lane = tid & 31;
    const int warp = tid >> 5;
    const int n0 = blockIdx.x * 128;
    const int m0 = blockIdx.y * 128;
    const int wm = (warp & 1) * 64;
    const int wn = (warp >> 1) * 32;
    const int fr = lane >> 2;
    const int fc = lane & 3;

    // ldmatrix lane addressing
    const int a_msel = (lane >> 3) & 1;
    const int a_ksel = lane >> 4;
    const int b_nsel = (lane >> 4) & 1;
    const int b_ksel = (lane >> 3) & 1;
    uint32_t a_off[4], a_sw[4], b_off[2], b_sw[2];
    #pragma unroll
    for (int mi = 0; mi < 4; mi++) {
        const int r = wm + mi*16 + a_msel*8 + (lane & 7);
        a_off[mi] = (uint32_t)r * 128;
        a_sw[mi]  = (uint32_t)(r & 7);
    }
    #pragma unroll
    for (int pi = 0; pi < 2; pi++) {
        const int n = wn + pi*16 + b_nsel*8 + (lane & 7);
        b_off[pi] = (uint32_t)n * 128;
        b_sw[pi]  = (uint32_t)(n & 7);
    }

    // loaders: A/B each 128 rows x 8 chunks, 2 thr/row, 4 chunks each
    const int lr  = tid >> 1;
    const int lj0 = (tid & 1) * 4;
    const __half* Ag = A + (size_t)(m0 + lr) * Cc;
    const __half* Wg = W + (size_t)(n0 + lr) * Cc;
    const uint32_t swr = (uint32_t)(lr & 7);

    float acc[4][4][4];
    #pragma unroll
    for (int i = 0; i < 4; i++)
        #pragma unroll
        for (int j = 0; j < 4; j++)
            #pragma unroll
            for (int q = 0; q < 4; q++) acc[i][j][q] = 0.f;

    #define G_LOAD(s, st) do {                                                  \
        const uint32_t sa = asb + (st) * G_TBY;                                  \
        const uint32_t sb = bsb + (st) * G_TBY;                                  \
        const int kof = (s) * G_BK;                                              \
        _Pragma("unroll")                                                        \
        for (int j = 0; j < 4; j++) {                                            \
            const int ch = lj0 + j;                                              \
            const uint32_t dof = lr*128 + (((uint32_t)ch ^ swr) << 4);           \
            cp_async16(sa + dof, Ag + kof + ch*8);                               \
            cp_async16(sb + dof, Wg + kof + ch*8);                               \
        }                                                                        \
    } while (0)

    G_LOAD(0, 0); cp_commit();
    G_LOAD(1, 1); cp_commit();

    for (int s = 0; s < G_NSTEP; s++) {
        cp_wait1();
        __syncthreads();
        if (s + 2 < G_NSTEP) { G_LOAD(s + 2, (s + 2) % G_STAGES); }
        cp_commit();

        const uint32_t A_sa = asb + (s % G_STAGES) * G_TBY;
        const uint32_t B_sa = bsb + (s % G_STAGES) * G_TBY;

        #pragma unroll
        for (int ks = 0; ks < 4; ks++) {
            const uint32_t ka  = (uint32_t)(2*ks + a_ksel);
            const uint32_t kb_ = (uint32_t)(2*ks + b_ksel);
            uint32_t af[4][4], bf[2][4];
            #pragma unroll
            for (int mi = 0; mi < 4; mi++)
                ldsm_x4(af[mi], A_sa + a_off[mi] + ((ka ^ a_sw[mi]) << 4));
            #pragma unroll
            for (int pi = 0; pi < 2; pi++)
                ldsm_x4(bf[pi], B_sa + b_off[pi] + ((kb_ ^ b_sw[pi]) << 4));
            #pragma unroll
            for (int mi = 0; mi < 4; mi++)
                #pragma unroll
                for (int ni = 0; ni < 4; ni++)
                    mma_f16(acc[mi][ni], af[mi], &bf[ni >> 1][(ni & 1) * 2]);
        }
    }
    #undef G_LOAD
    __syncthreads();

    #pragma unroll
    for (int mi = 0; mi < 4; mi++) {
        const int r0 = m0 + wm + mi*16 + fr;
        #pragma unroll
        for (int ni = 0; ni < 4; ni++) {
            const int col = n0 + wn + ni*8 + fc*2;
            if (HALF_OUT) {
                *(__half2*)(Ch + (size_t)r0       * Cc + col) =
                    __floats2half2_rn(acc[mi][ni][0], acc[mi][ni][1]);
                *(__half2*)(Ch + (size_t)(r0 + 8) * Cc + col) =
                    __floats2half2_rn(acc[mi][ni][2], acc[mi][ni][3]);
            } else {
                const float b0 = __ldg(bias + col), b1 = __ldg(bias + col + 1);
                *(float2*)(Cf + (size_t)r0       * Cc + col) =
                    make_float2(acc[mi][ni][0] + b0, acc[mi][ni][1] + b1);
                *(float2*)(Cf + (size_t)(r0 + 8) * Cc + col) =
                    make_float2(acc[mi][ni][2] + b0, acc[mi][ni][3] + b1);
            }
        }
    }
}

__global__ void __launch_bounds__(256, 2)
gemm_out(const __half* __restrict__ A, const __half* __restrict__ W,
         const float* __restrict__ bias, float* __restrict__ C) {
    gemm_body<false>(A, W, bias, C, nullptr);
}

__global__ void __launch_bounds__(256, 2)
gemm_qkv(const __half* __restrict__ A,
         const __half* __restrict__ W0, const __half* __restrict__ W1,
         const __half* __restrict__ W2,
         __half* __restrict__ C0, __half* __restrict__ C1, __half* __restrict__ C2) {
    const __half* W = (blockIdx.z == 0) ? W0 : (blockIdx.z == 1) ? W1 : W2;
    __half*       C = (blockIdx.z == 0) ? C0 : (blockIdx.z == 1) ? C1 : C2;
    gemm_body<true>(A, W, nullptr, nullptr, C);
}

// ===========================================================================
// Flash-attention, fp16 mma.sync, double-buffered K/V (unchanged from R9).
// CTA = 128 threads, one (b,h,64-query tile). smem 88KB -> 2 CTAs/SM.
// ===========================================================================
#define AT_Q  0
#define AT_K0 16384
#define AT_V0 49152
#define AT_P  81920
#define AT_SMEM 90112

__global__ void __launch_bounds__(128, 2) attn_f16(const int* __restrict__ pm)
{
    extern __shared__ char smc[];
    const uint32_t sb  = smem_u32(smc);
    const uint32_t qsb = sb + AT_Q;
    const uint32_t psb = sb + AT_P;

    const int qb = (gridDim.x - 1) - blockIdx.x;   // descending order
    const int h  = blockIdx.y;
    const int b  = blockIdx.z;
    const int tid  = threadIdx.x;
    const int lane = tid & 31;
    const int warp = tid >> 5;
    const int fr = lane >> 2;
    const int fc = lane & 3;

    const int a_msel = (lane >> 3) & 1;
    const int a_ksel = lane >> 4;
    const int b_nsel = (lane >> 4) & 1;
    const int b_ksel = (lane >> 3) & 1;
    const int v_ssel = (lane >> 3) & 1;
    const int v_dsel = (lane >> 4) & 1;
    const int a_row  = warp*16 + a_msel*8 + (lane & 7);

    const size_t hoff = (size_t)h * Dd;
    const __half* Qg = g_qh + (size_t)b * Tt * Cc + hoff;
    const __half* Kg = g_kh + (size_t)b * Tt * Cc + hoff;
    const __half* Vg = g_vh + (size_t)b * Tt * Cc + hoff;
    const int q0 = qb * 64;

    const int lrow = tid >> 1;
    const int lch0 = (tid & 1) * 8;
    const uint32_t lsw = (uint32_t)(lrow & 7);

    #define AT_LOADKV(kt, st) do {                                                 \
        const uint32_t kb_ = sb + AT_K0 + (st)*16384;                              \
        const uint32_t vb_ = sb + AT_V0 + (st)*16384;                              \
        _Pragma("unroll")                                                          \
        for (int j = 0; j < 8; j++) {                                              \
            const int ch = lch0 + j;                                               \
            const uint32_t doff = lrow*256 + (((uint32_t)ch ^ lsw) << 4);          \
            cp_async16(kb_ + doff, Kg + (size_t)((kt)*64 + lrow)*Cc + ch*8);       \
            cp_async16(vb_ + doff, Vg + (size_t)((kt)*64 + lrow)*Cc + ch*8);       \
        }                                                                          \
        cp_commit();                                                               \
    } while (0)

    #pragma unroll
    for (int j = 0; j < 8; j++) {
        const int ch = lch0 + j;
        cp_async16(qsb + lrow*256 + (((uint32_t)ch ^ lsw) << 4),
                   Qg + (size_t)(q0 + lrow)*Cc + ch*8);
    }
    cp_commit();
    AT_LOADKV(0, 0);
    cp_wait1();
    __syncthreads();

    uint32_t qf[8][4];
    #pragma unroll
    for (int kb = 0; kb < 8; kb++)
        ldsm_x4(qf[kb], qsb + a_row*256 + (((uint32_t)(2*kb + a_ksel) ^ (uint32_t)(a_row & 7)) << 4));

    const float scale = 0.08838834764831845f;
    const int rowA = q0 + warp*16 + fr;
    const int rowB = rowA + 8;
    const int pmA = pm[b*Tt + rowA];
    const int pmB = pm[b*Tt + rowB];
    const int prA = warp*16 + fr;

    float o[16][4];
    #pragma unroll
    for (int i = 0; i < 16; i++)
        #pragma unroll
        for (int j = 0; j < 4; j++) o[i][j] = 0.f;
    float mA = -INFINITY, mB = -INFINITY, lA = 0.f, lB = 0.f;

    for (int kt = 0; kt <= qb; kt++) {
        const int cur = kt & 1;
        const bool more = (kt + 1 <= qb);
        if (more) AT_LOADKV(kt + 1, cur ^ 1);
        if (more) cp_wait1(); else cp_wait0();
        __syncthreads();

        const uint32_t ksb = sb + AT_K0 + cur*16384;
        const uint32_t vsb = sb + AT_V0 + cur*16384;

        float sa[8][4];
        #pragma unroll
        for (int ni = 0; ni < 8; ni++)
            #pragma unroll
            for (int j = 0; j < 4; j++) sa[ni][j] = 0.f;

        #pragma unroll
        for (int kb = 0; kb < 8; kb++) {
            uint32_t bq[4][4];
            #pragma unroll
            for (int pi = 0; pi < 4; pi++) {
                const int n = pi*16 + b_nsel*8 + (lane & 7);
                ldsm_x4(bq[pi], ksb + n*256 + (((uint32_t)(2*kb + b_ksel) ^ (uint32_t)(n & 7)) << 4));
            }
            #pragma unroll
            for (int ni = 0; ni < 8; ni++)
                mma_f16(sa[ni], qf[kb], &bq[ni >> 1][(ni & 1) * 2]);
        }

        float mxA = -INFINITY, mxB = -INFINITY;
        #pragma unroll
        for (int ni = 0; ni < 8; ni++) {
            const int c0 = kt*64 + ni*8 + 2*fc;
            float s0 = sa[ni][0]*scale, s1 = sa[ni][1]*scale;
            float s2 = sa[ni][2]*scale, s3 = sa[ni][3]*scale;
            if (pmA == 0) { s0 = -1e9f; s1 = -1e9f; }
            if (pmB == 0) { s2 = -1e9f; s3 = -1e9f; }
            if (kt == qb) {
                if (c0     > rowA) s0 = -INFINITY;
                if (c0 + 1 > rowA) s1 = -INFINITY;
                if (c0     > rowB) s2 = -INFINITY;
                if (c0 + 1 > rowB) s3 = -INFINITY;
            }
            sa[ni][0] = s0; sa[ni][1] = s1; sa[ni][2] = s2; sa[ni][3] = s3;
            mxA = fmaxf(mxA, fmaxf(s0, s1));
            mxB = fmaxf(mxB, fmaxf(s2, s3));
        }
        mxA = fmaxf(mxA, __shfl_xor_sync(0xffffffffu, mxA, 1));
        mxA = fmaxf(mxA, __shfl_xor_sync(0xffffffffu, mxA, 2));
        mxB = fmaxf(mxB, __shfl_xor_sync(0xffffffffu, mxB, 1));
        mxB = fmaxf(mxB, __shfl_xor_sync(0xffffffffu, mxB, 2));

        const float mnA = fmaxf(mA, mxA), mnB = fmaxf(mB, mxB);
        const float sfA = __expf(mA - mnA), sfB = __expf(mB - mnB);
        mA = mnA; mB = mnB;

        float suA = 0.f, suB = 0.f;
        #pragma unroll
        for (int ni = 0; ni < 8; ni++) {
            __half2 h01 = __floats2half2_rn(__expf(sa[ni][0] - mA), __expf(sa[ni][1] - mA));
            __half2 h23 = __floats2half2_rn(__expf(sa[ni][2] - mB), __expf(sa[ni][3] - mB));
            const float2 f01 = __half22float2(h01);
            const float2 f23 = __half22float2(h23);
            suA += f01.x + f01.y; suB += f23.x + f23.y;
            const uint32_t aoA = psb + prA*128     + (((uint32_t)ni ^ (uint32_t)(prA & 7))     << 4) + fc*4;
            const uint32_t aoB = psb + (prA+8)*128 + (((uint32_t)ni ^ (uint32_t)((prA+8) & 7)) << 4) + fc*4;
            *(__half2*)(smc + (aoA - sb)) = h01;
            *(__half2*)(smc + (aoB - sb)) = h23;
        }
        suA += __shfl_xor_sync(0xffffffffu, suA, 1);
        suA += __shfl_xor_sync(0xffffffffu, suA, 2);
        suB += __shfl_xor_sync(0xffffffffu, suB, 1);
        suB += __shfl_xor_sync(0xffffffffu, suB, 2);
        lA = lA*sfA + suA;
        lB = lB*sfB + suB;
        #pragma unroll
        for (int ni = 0; ni < 16; ni++) {
            o[ni][0] *= sfA; o[ni][1] *= sfA;
            o[ni][2] *= sfB; o[ni][3] *= sfB;
        }
        __syncwarp();

        #pragma unroll
        for (int kb = 0; kb < 4; kb++) {
            uint32_t pa[4];
            ldsm_x4(pa, psb + a_row*128 + (((uint32_t)(2*kb + a_ksel) ^ (uint32_t)(a_row & 7)) << 4));
            #pragma unroll
            for (int di = 0; di < 8; di++) {
                uint32_t bv[4];
                const int sv = kb*16 + v_ssel*8 + (lane & 7);
                const uint32_t ch = (uint32_t)(2*di + v_dsel);
                ldsm_x4_t(bv, vsb + sv*256 + ((ch ^ (uint32_t)(sv & 7)) << 4));
                mma_f16(o[di*2    ], pa, &bv[0]);
                mma_f16(o[di*2 + 1], pa, &bv[2]);
            }
        }
        __syncthreads();
    }
    #undef AT_LOADKV

    const float iA = 1.f / lA, iB = 1.f / lB;
    __half* cpA = g_ctxh + (size_t)(b*Tt + rowA)*Cc + hoff;
    __half* cpB = g_ctxh + (size_t)(b*Tt + rowB)*Cc + hoff;
    #pragma unroll
    for (int ni = 0; ni < 16; ni++) {
        const int d0 = ni*8 + 2*fc;
        *(__half2*)(cpA + d0) = __floats2half2_rn(o[ni][0]*iA, o[ni][1]*iA);
        *(__half2*)(cpB + d0) = __floats2half2_rn(o[ni][2]*iB, o[ni][3]*iB);
    }
}

// ===========================================================================
extern "C" void kernel_launch(void* const* d_in, const int* in_sizes, int n_in,
                              void* d_out, int out_size)
{
    (void)in_sizes; (void)n_in; (void)out_size;
    const float* x  = (const float*)d_in[0];
    const int*   pm = (const int*)  d_in[1];
    const float* Wq = (const float*)d_in[2];
    const float* Wk = (const float*)d_in[3];
    const float* Wv = (const float*)d_in[4];
    const float* Wp = (const float*)d_in[5];
    const float* bp = (const float*)d_in[6];
    float* out = (float*)d_out;

    __half *xh, *wqh, *wkh, *wvh, *wph, *qh, *kh, *vh, *ctxh;
    cudaGetSymbolAddress((void**)&xh,   g_xh);
    cudaGetSymbolAddress((void**)&wqh,  g_wqh);
    cudaGetSymbolAddress((void**)&wkh,  g_wkh);
    cudaGetSymbolAddress((void**)&wvh,  g_wvh);
    cudaGetSymbolAddress((void**)&wph,  g_wph);
    cudaGetSymbolAddress((void**)&qh,   g_qh);
    cudaGetSymbolAddress((void**)&kh,   g_kh);
    cudaGetSymbolAddress((void**)&vh,   g_vh);
    cudaGetSymbolAddress((void**)&ctxh, g_ctxh);

    const int nb = (NTOK*Cc/4 + 255) / 256;
    tohalf_all<<<dim3(nb, 1, 5), 256>>>(
        (const float4*)x,  xh,
        (const float4*)Wq, wqh,
        (const float4*)Wk, wkh,
        (const float4*)Wv, wvh,
        (const float4*)Wp, wph);

    cudaFuncSetAttribute(gemm_qkv, cudaFuncAttributeMaxDynamicSharedMemorySize, G_SMEM);
    cudaFuncSetAttribute(gemm_out, cudaFuncAttributeMaxDynamicSharedMemorySize, G_SMEM);
    cudaFuncSetAttribute(attn_f16, cudaFuncAttributeMaxDynamicSharedMemorySize, AT_SMEM);

    gemm_qkv<<<dim3(Cc/128, NTOK/128, 3), 256, G_SMEM>>>(xh, wqh, wkh, wvh, qh, kh, vh);
    attn_f16<<<dim3(Tt/64, Hh, Bb), 128, AT_SMEM>>>(pm);
    gemm_out<<<dim3(Cc/128, NTOK/128), 256, G_SMEM>>>(ctxh, wph, bp, out);
}